// round 6
// baseline (speedup 1.0000x reference)
#include <cuda_runtime.h>
#include <cuda_fp16.h>

#define NN 100000
#define NE 1600000
#define FIN 128
#define FH  64
#define FO  10

#define SCAN_BLK 512
#define NSCAN ((NN + SCAN_BLK - 1) / SCAN_BLK)   // 196

typedef unsigned long long u64;

// ---- scratch (device globals; no allocation allowed) ----
__device__ int   g_indeg[NN];
__device__ int   g_off[NN];
__device__ int   g_cursor[NN];
__device__ int   g_offp[NN];
__device__ int   g_bsum[NSCAN];
__device__ int   g_csrc[NE];
__device__ float g_dinv[NN];
__device__ __align__(16) __half g_hs[NN * FH];   // (x@W1) * dinv[row], fp16
__device__ __align__(16) float  g_agg[NN * FH];  // relu(b1 + dinv*(hs[d]+sum hs[src]))
__device__ __align__(16) __half g_h2s[NN * 16];  // (agg@W2) * dinv[row], fp16, stride 16

// ---- packed f32x2 helpers ----
__device__ __forceinline__ u64 dup2(float v) {
    u64 d; asm("mov.b64 %0, {%1,%1};" : "=l"(d) : "f"(v)); return d;
}
__device__ __forceinline__ void ffma2(u64& d, u64 a, u64 b) {
    asm("fma.rn.f32x2 %0, %1, %2, %0;" : "+l"(d) : "l"(a), "l"(b));
}
__device__ __forceinline__ float2 unpack2(u64 d) {
    float lo, hi; asm("mov.b64 {%0,%1}, %2;" : "=f"(lo), "=f"(hi) : "l"(d));
    return make_float2(lo, hi);
}
__device__ __forceinline__ unsigned h2_bits(__half2 h) {
    return *reinterpret_cast<unsigned*>(&h);
}

// ================= degree =================
__global__ void k_zero() {
    int i = blockIdx.x * blockDim.x + threadIdx.x;
    if (i < NN) g_indeg[i] = 0;
}
__global__ void k_indeg(const int* __restrict__ dst) {
    int e = blockIdx.x * blockDim.x + threadIdx.x;
    if (e < NE) atomicAdd(&g_indeg[dst[e]], 1);
}

// ================= scan pass 1 (+ dinv fused) =================
__global__ void __launch_bounds__(SCAN_BLK) k_scan1() {
    int i = blockIdx.x * SCAN_BLK + threadIdx.x;
    int v = (i < NN) ? g_indeg[i] : 0;
    if (i < NN) g_dinv[i] = rsqrtf(1.0f + (float)v);
    int lane = threadIdx.x & 31, w = threadIdx.x >> 5;
    int s = v;
#pragma unroll
    for (int o = 1; o < 32; o <<= 1) {
        int t = __shfl_up_sync(0xffffffffu, s, o);
        if (lane >= o) s += t;
    }
    __shared__ int wsum[16];
    if (lane == 31) wsum[w] = s;
    __syncthreads();
    if (w == 0) {
        int t = (lane < 16) ? wsum[lane] : 0;
#pragma unroll
        for (int o = 1; o < 16; o <<= 1) {
            int u = __shfl_up_sync(0xffffffffu, t, o);
            if (lane >= o) t += u;
        }
        if (lane < 16) wsum[lane] = t;
    }
    __syncthreads();
    int excl = s - v + ((w > 0) ? wsum[w - 1] : 0);
    if (i < NN) g_offp[i] = excl;
    if (threadIdx.x == 0) g_bsum[blockIdx.x] = wsum[15];
}

// ===== scan pass 2 fused into apply: every block scans the 196 block sums =====
__global__ void __launch_bounds__(256) k_scan_apply() {
    __shared__ int s_ex[256];
    int tid = threadIdx.x;
    {
        int v = (tid < NSCAN) ? g_bsum[tid] : 0;
        int lane = tid & 31, w = tid >> 5;
        int s = v;
#pragma unroll
        for (int o = 1; o < 32; o <<= 1) {
            int t = __shfl_up_sync(0xffffffffu, s, o);
            if (lane >= o) s += t;
        }
        __shared__ int wsum[8];
        if (lane == 31) wsum[w] = s;
        __syncthreads();
        if (w == 0) {
            int t = (lane < 8) ? wsum[lane] : 0;
#pragma unroll
            for (int o = 1; o < 8; o <<= 1) {
                int u = __shfl_up_sync(0xffffffffu, t, o);
                if (lane >= o) t += u;
            }
            if (lane < 8) wsum[lane] = t;
        }
        __syncthreads();
        s_ex[tid] = s - v + ((w > 0) ? wsum[w - 1] : 0);  // exclusive
        __syncthreads();
    }
    int i = blockIdx.x * 256 + tid;
    if (i < NN) {
        int o = g_offp[i] + s_ex[i >> 9];
        g_off[i] = o;
        g_cursor[i] = o;
    }
}

// ================= CSR positional scatter =================
__global__ void k_edge_pos(const int* __restrict__ src, const int* __restrict__ dst) {
    int e = blockIdx.x * blockDim.x + threadIdx.x;
    if (e < NE) {
        int pos = atomicAdd(&g_cursor[dst[e]], 1);
        g_csrc[pos] = src[e];
    }
}

// ================= GEMM1: hs = half(x @ W1 * dinv[row]) =================
#define XS_F4 (256 * 17)
#define GEMM1_SMEM (XS_F4 * 16 + 64 * 64 * 4)   // 86016 B

__global__ void __launch_bounds__(256, 2) k_gemm1(const float* __restrict__ x,
                                                  const float* __restrict__ W1) {
    extern __shared__ float4 sm4[];
    float4* xs4 = sm4;                     // [256][17]
    float*  Ws  = (float*)(sm4 + XS_F4);   // [64][64]

    const int tid = threadIdx.x;
    const int c  = tid & 7;
    const int rg = tid >> 3;
    const int row_base = blockIdx.x * 256;

    u64 acc[8][4];
#pragma unroll
    for (int i = 0; i < 8; i++)
#pragma unroll
        for (int p = 0; p < 4; p++) acc[i][p] = 0ull;

    const float4* x4  = reinterpret_cast<const float4*>(x);
    const float4* W14 = reinterpret_cast<const float4*>(W1);
    float4* Ws4 = reinterpret_cast<float4*>(Ws);

    for (int kc = 0; kc < 2; kc++) {
#pragma unroll
        for (int j = 0; j < 16; j++) {
            int f = tid + 256 * j;
            int row = f >> 4;
            int kq  = f & 15;
            int grow = min(row_base + row, NN - 1);
            xs4[row * 17 + kq] = x4[(size_t)grow * 32 + kc * 16 + kq];
        }
#pragma unroll
        for (int j = 0; j < 4; j++) {
            int f = tid + 256 * j;
            Ws4[f] = W14[kc * 1024 + f];
        }
        __syncthreads();

#define ROWSTEP(i, comp)                                   \
        {                                                  \
            u64 xd = dup2(xq[i].comp);                     \
            ffma2(acc[i][0], xd, wA.x);                    \
            ffma2(acc[i][1], xd, wA.y);                    \
            ffma2(acc[i][2], xd, wB.x);                    \
            ffma2(acc[i][3], xd, wB.y);                    \
        }
#define KSTEP(comp, kk)                                                        \
        {                                                                      \
            const ulonglong2* wr =                                             \
                (const ulonglong2*)(Ws + (k4 * 4 + kk) * 64 + c * 8);          \
            ulonglong2 wA = wr[0];                                             \
            ulonglong2 wB = wr[1];                                             \
            ROWSTEP(0, comp) ROWSTEP(1, comp) ROWSTEP(2, comp) ROWSTEP(3, comp)\
            ROWSTEP(4, comp) ROWSTEP(5, comp) ROWSTEP(6, comp) ROWSTEP(7, comp)\
        }

#pragma unroll 4
        for (int k4 = 0; k4 < 16; k4++) {
            float4 xq[8];
#pragma unroll
            for (int i = 0; i < 8; i++) xq[i] = xs4[(rg + 32 * i) * 17 + k4];
            KSTEP(x, 0)
            KSTEP(y, 1)
            KSTEP(z, 2)
            KSTEP(w, 3)
        }
        __syncthreads();
    }

    uint4* hs16 = reinterpret_cast<uint4*>(g_hs);
#pragma unroll
    for (int i = 0; i < 8; i++) {
        int grow = row_base + rg + 32 * i;
        if (grow < NN) {
            float di = g_dinv[grow];
            float2 p0 = unpack2(acc[i][0]);
            float2 p1 = unpack2(acc[i][1]);
            float2 p2 = unpack2(acc[i][2]);
            float2 p3 = unpack2(acc[i][3]);
            __half2 h0 = __float22half2_rn(make_float2(p0.x * di, p0.y * di));
            __half2 h1 = __float22half2_rn(make_float2(p1.x * di, p1.y * di));
            __half2 h2 = __float22half2_rn(make_float2(p2.x * di, p2.y * di));
            __half2 h3 = __float22half2_rn(make_float2(p3.x * di, p3.y * di));
            uint4 u;
            u.x = h2_bits(h0);
            u.y = h2_bits(h1);
            u.z = h2_bits(h2);
            u.w = h2_bits(h3);
            hs16[(size_t)grow * 8 + c] = u;
        }
    }
#undef KSTEP
#undef ROWSTEP
}

// ================= agg1: warp-per-node, smem edge staging, unrolled gather =====
__global__ void __launch_bounds__(256) k_agg1(const float* __restrict__ b1) {
    __shared__ int s_idx[8][32];
    const int w = threadIdx.x >> 5;
    const int lane = threadIdx.x & 31;
    const int d = blockIdx.x * 8 + w;
    if (d >= NN) return;

    const __half2* hs2 = reinterpret_cast<const __half2*>(g_hs);
    float2 acc = __half22float2(hs2[(size_t)d * 32 + lane]);

    const int beg = g_off[d];
    const int cnt = g_indeg[d];
    for (int base = 0; base < cnt; base += 32) {
        int take = cnt - base;
        if (take > 32) take = 32;
        if (lane < take) s_idx[w][lane] = g_csrc[beg + base + lane];
        __syncwarp();
#pragma unroll
        for (int j = 0; j < 32; j++) {
            if (j < take) {
                int sj = s_idx[w][j];
                float2 v = __half22float2(hs2[(size_t)sj * 32 + lane]);
                acc.x += v.x;
                acc.y += v.y;
            }
        }
        __syncwarp();
    }

    float di = g_dinv[d];
    float2 b = reinterpret_cast<const float2*>(b1)[lane];
    float2 o;
    o.x = fmaxf(fmaf(acc.x, di, b.x), 0.0f);
    o.y = fmaxf(fmaf(acc.y, di, b.y), 0.0f);
    reinterpret_cast<float2*>(g_agg)[(size_t)d * 32 + lane] = o;
}

// ========== GEMM2: h2s = half((agg @ W2) * dinv[row]), fp16 stride-16 ==========
__global__ void __launch_bounds__(256) k_gemm2(const float* __restrict__ W2) {
    __shared__ float Ws[FH * FO];
    for (int i = threadIdx.x; i < FH * FO; i += blockDim.x) Ws[i] = W2[i];
    __syncthreads();

    int n = blockIdx.x * blockDim.x + threadIdx.x;
    if (n >= NN) return;

    float acc[FO];
#pragma unroll
    for (int j = 0; j < FO; j++) acc[j] = 0.0f;

    const float4* a4 = reinterpret_cast<const float4*>(g_agg + (size_t)n * FH);
#pragma unroll
    for (int k4 = 0; k4 < 16; k4++) {
        float4 a = a4[k4];
        float av[4] = {a.x, a.y, a.z, a.w};
#pragma unroll
        for (int kk = 0; kk < 4; kk++) {
            int k = k4 * 4 + kk;
#pragma unroll
            for (int j = 0; j < FO; j++) acc[j] = fmaf(av[kk], Ws[k * FO + j], acc[j]);
        }
    }

    float di = g_dinv[n];
    unsigned* o2 = reinterpret_cast<unsigned*>(g_h2s + (size_t)n * 16);
#pragma unroll
    for (int p = 0; p < 5; p++) {
        __half2 h = __float22half2_rn(make_float2(acc[p * 2] * di, acc[p * 2 + 1] * di));
        o2[p] = h2_bits(h);
    }
}

// ===== agg2: warp-per-node gather (fp16 rows, 5 active lanes as half2) =====
__global__ void __launch_bounds__(256) k_agg2(const float* __restrict__ b2,
                                              float* __restrict__ out) {
    __shared__ int s_idx[8][32];
    const int w = threadIdx.x >> 5;
    const int lane = threadIdx.x & 31;
    const int d = blockIdx.x * 8 + w;
    if (d >= NN) return;

    const __half2* h2p = reinterpret_cast<const __half2*>(g_h2s);
    float2 acc = make_float2(0.f, 0.f);
    if (lane < 5) acc = __half22float2(h2p[(size_t)d * 8 + lane]);

    const int beg = g_off[d];
    const int cnt = g_indeg[d];
    for (int base = 0; base < cnt; base += 32) {
        int take = cnt - base;
        if (take > 32) take = 32;
        if (lane < take) s_idx[w][lane] = g_csrc[beg + base + lane];
        __syncwarp();
#pragma unroll
        for (int j = 0; j < 32; j++) {
            if (j < take && lane < 5) {
                int sj = s_idx[w][j];
                float2 v = __half22float2(h2p[(size_t)sj * 8 + lane]);
                acc.x += v.x;
                acc.y += v.y;
            }
        }
        __syncwarp();
    }

    if (lane < 5) {
        float di = g_dinv[d];
        float* op = out + (size_t)d * FO;
        op[lane * 2]     = fmaf(acc.x, di, b2[lane * 2]);
        op[lane * 2 + 1] = fmaf(acc.y, di, b2[lane * 2 + 1]);
    }
}

extern "C" void kernel_launch(void* const* d_in, const int* in_sizes, int n_in,
                              void* d_out, int out_size) {
    const float* x  = (const float*)d_in[0];
    const int*   ei = (const int*)d_in[1];
    const float* W1 = (const float*)d_in[2];
    const float* b1 = (const float*)d_in[3];
    const float* W2 = (const float*)d_in[4];
    const float* b2 = (const float*)d_in[5];
    float* out = (float*)d_out;

    const int* src = ei;
    const int* dst = ei + NE;

    static bool attr_set = false;
    if (!attr_set) {
        cudaFuncSetAttribute(k_gemm1, cudaFuncAttributeMaxDynamicSharedMemorySize,
                             GEMM1_SMEM);
        attr_set = true;
    }

    k_zero<<<(NN + 255) / 256, 256>>>();
    k_indeg<<<(NE + 255) / 256, 256>>>(dst);
    k_scan1<<<NSCAN, SCAN_BLK>>>();
    k_scan_apply<<<(NN + 255) / 256, 256>>>();
    k_edge_pos<<<(NE + 255) / 256, 256>>>(src, dst);
    k_gemm1<<<(NN + 255) / 256, 256, GEMM1_SMEM>>>(x, W1);
    k_agg1<<<(NN + 7) / 8, 256>>>(b1);
    k_gemm2<<<(NN + 255) / 256, 256>>>(W2);
    k_agg2<<<(NN + 7) / 8, 256>>>(b2, out);
}

// round 7
// speedup vs baseline: 1.1809x; 1.1809x over previous
#include <cuda_runtime.h>
#include <cuda_fp16.h>

#define NN 100000
#define NE 1600000
#define FIN 128
#define FH  64
#define FO  10

#define SCAN_BLK 512
#define NSCAN ((NN + SCAN_BLK - 1) / SCAN_BLK)   // 196

typedef unsigned long long u64;

// ---- scratch (device globals; no allocation allowed) ----
__device__ int   g_indeg[NN];
__device__ int   g_off[NN];
__device__ int   g_cursor[NN];
__device__ int   g_offp[NN];
__device__ int   g_bsum[NSCAN];
__device__ int   g_csrc[NE];
__device__ float g_dinv[NN];
__device__ __align__(16) __half g_hs[NN * FH];   // (x@W1) * dinv[row], fp16
__device__ __align__(16) float  g_agg[NN * FH];  // relu(b1 + dinv*(hs[d]+sum hs[src]))
__device__ __align__(16) __half g_h2s[NN * 16];  // (agg@W2) * dinv[row], fp16, stride 16

// ---- packed f32x2 helpers ----
__device__ __forceinline__ u64 dup2(float v) {
    u64 d; asm("mov.b64 %0, {%1,%1};" : "=l"(d) : "f"(v)); return d;
}
__device__ __forceinline__ void ffma2(u64& d, u64 a, u64 b) {
    asm("fma.rn.f32x2 %0, %1, %2, %0;" : "+l"(d) : "l"(a), "l"(b));
}
__device__ __forceinline__ float2 unpack2(u64 d) {
    float lo, hi; asm("mov.b64 {%0,%1}, %2;" : "=f"(lo), "=f"(hi) : "l"(d));
    return make_float2(lo, hi);
}
__device__ __forceinline__ unsigned h2_bits(__half2 h) {
    return *reinterpret_cast<unsigned*>(&h);
}

// ================= degree =================
__global__ void k_zero() {
    int i = blockIdx.x * blockDim.x + threadIdx.x;
    if (i < NN) g_indeg[i] = 0;
}
__global__ void k_indeg(const int* __restrict__ dst) {
    int e = blockIdx.x * blockDim.x + threadIdx.x;
    if (e < NE) atomicAdd(&g_indeg[dst[e]], 1);
}

// ================= scan pass 1 (+ dinv fused) =================
__global__ void __launch_bounds__(SCAN_BLK) k_scan1() {
    int i = blockIdx.x * SCAN_BLK + threadIdx.x;
    int v = (i < NN) ? g_indeg[i] : 0;
    if (i < NN) g_dinv[i] = rsqrtf(1.0f + (float)v);
    int lane = threadIdx.x & 31, w = threadIdx.x >> 5;
    int s = v;
#pragma unroll
    for (int o = 1; o < 32; o <<= 1) {
        int t = __shfl_up_sync(0xffffffffu, s, o);
        if (lane >= o) s += t;
    }
    __shared__ int wsum[16];
    if (lane == 31) wsum[w] = s;
    __syncthreads();
    if (w == 0) {
        int t = (lane < 16) ? wsum[lane] : 0;
#pragma unroll
        for (int o = 1; o < 16; o <<= 1) {
            int u = __shfl_up_sync(0xffffffffu, t, o);
            if (lane >= o) t += u;
        }
        if (lane < 16) wsum[lane] = t;
    }
    __syncthreads();
    int excl = s - v + ((w > 0) ? wsum[w - 1] : 0);
    if (i < NN) g_offp[i] = excl;
    if (threadIdx.x == 0) g_bsum[blockIdx.x] = wsum[15];
}

// ===== scan pass 2 fused into apply: every block scans the 196 block sums =====
__global__ void __launch_bounds__(256) k_scan_apply() {
    __shared__ int s_ex[256];
    int tid = threadIdx.x;
    {
        int v = (tid < NSCAN) ? g_bsum[tid] : 0;
        int lane = tid & 31, w = tid >> 5;
        int s = v;
#pragma unroll
        for (int o = 1; o < 32; o <<= 1) {
            int t = __shfl_up_sync(0xffffffffu, s, o);
            if (lane >= o) s += t;
        }
        __shared__ int wsum[8];
        if (lane == 31) wsum[w] = s;
        __syncthreads();
        if (w == 0) {
            int t = (lane < 8) ? wsum[lane] : 0;
#pragma unroll
            for (int o = 1; o < 8; o <<= 1) {
                int u = __shfl_up_sync(0xffffffffu, t, o);
                if (lane >= o) t += u;
            }
            if (lane < 8) wsum[lane] = t;
        }
        __syncthreads();
        s_ex[tid] = s - v + ((w > 0) ? wsum[w - 1] : 0);  // exclusive
        __syncthreads();
    }
    int i = blockIdx.x * 256 + tid;
    if (i < NN) {
        int o = g_offp[i] + s_ex[i >> 9];
        g_off[i] = o;
        g_cursor[i] = o;
    }
}

// ================= CSR positional scatter =================
__global__ void k_edge_pos(const int* __restrict__ src, const int* __restrict__ dst) {
    int e = blockIdx.x * blockDim.x + threadIdx.x;
    if (e < NE) {
        int pos = atomicAdd(&g_cursor[dst[e]], 1);
        g_csrc[pos] = src[e];
    }
}

// ================= GEMM1: hs = half(x @ W1 * dinv[row]) =================
#define XS_F4 (256 * 17)
#define GEMM1_SMEM (XS_F4 * 16 + 64 * 64 * 4)   // 86016 B

__global__ void __launch_bounds__(256, 2) k_gemm1(const float* __restrict__ x,
                                                  const float* __restrict__ W1) {
    extern __shared__ float4 sm4[];
    float4* xs4 = sm4;                     // [256][17]
    float*  Ws  = (float*)(sm4 + XS_F4);   // [64][64]

    const int tid = threadIdx.x;
    const int c  = tid & 7;
    const int rg = tid >> 3;
    const int row_base = blockIdx.x * 256;

    u64 acc[8][4];
#pragma unroll
    for (int i = 0; i < 8; i++)
#pragma unroll
        for (int p = 0; p < 4; p++) acc[i][p] = 0ull;

    const float4* x4  = reinterpret_cast<const float4*>(x);
    const float4* W14 = reinterpret_cast<const float4*>(W1);
    float4* Ws4 = reinterpret_cast<float4*>(Ws);

    for (int kc = 0; kc < 2; kc++) {
#pragma unroll
        for (int j = 0; j < 16; j++) {
            int f = tid + 256 * j;
            int row = f >> 4;
            int kq  = f & 15;
            int grow = min(row_base + row, NN - 1);
            xs4[row * 17 + kq] = x4[(size_t)grow * 32 + kc * 16 + kq];
        }
#pragma unroll
        for (int j = 0; j < 4; j++) {
            int f = tid + 256 * j;
            Ws4[f] = W14[kc * 1024 + f];
        }
        __syncthreads();

#define ROWSTEP(i, comp)                                   \
        {                                                  \
            u64 xd = dup2(xq[i].comp);                     \
            ffma2(acc[i][0], xd, wA.x);                    \
            ffma2(acc[i][1], xd, wA.y);                    \
            ffma2(acc[i][2], xd, wB.x);                    \
            ffma2(acc[i][3], xd, wB.y);                    \
        }
#define KSTEP(comp, kk)                                                        \
        {                                                                      \
            const ulonglong2* wr =                                             \
                (const ulonglong2*)(Ws + (k4 * 4 + kk) * 64 + c * 8);          \
            ulonglong2 wA = wr[0];                                             \
            ulonglong2 wB = wr[1];                                             \
            ROWSTEP(0, comp) ROWSTEP(1, comp) ROWSTEP(2, comp) ROWSTEP(3, comp)\
            ROWSTEP(4, comp) ROWSTEP(5, comp) ROWSTEP(6, comp) ROWSTEP(7, comp)\
        }

#pragma unroll 4
        for (int k4 = 0; k4 < 16; k4++) {
            float4 xq[8];
#pragma unroll
            for (int i = 0; i < 8; i++) xq[i] = xs4[(rg + 32 * i) * 17 + k4];
            KSTEP(x, 0)
            KSTEP(y, 1)
            KSTEP(z, 2)
            KSTEP(w, 3)
        }
        __syncthreads();
    }

    uint4* hs16 = reinterpret_cast<uint4*>(g_hs);
#pragma unroll
    for (int i = 0; i < 8; i++) {
        int grow = row_base + rg + 32 * i;
        if (grow < NN) {
            float di = g_dinv[grow];
            float2 p0 = unpack2(acc[i][0]);
            float2 p1 = unpack2(acc[i][1]);
            float2 p2 = unpack2(acc[i][2]);
            float2 p3 = unpack2(acc[i][3]);
            __half2 h0 = __float22half2_rn(make_float2(p0.x * di, p0.y * di));
            __half2 h1 = __float22half2_rn(make_float2(p1.x * di, p1.y * di));
            __half2 h2 = __float22half2_rn(make_float2(p2.x * di, p2.y * di));
            __half2 h3 = __float22half2_rn(make_float2(p3.x * di, p3.y * di));
            uint4 u;
            u.x = h2_bits(h0);
            u.y = h2_bits(h1);
            u.z = h2_bits(h2);
            u.w = h2_bits(h3);
            hs16[(size_t)grow * 8 + c] = u;
        }
    }
#undef KSTEP
#undef ROWSTEP
}

// ================= agg1: warp-per-node gather-sum (shfl indices, fp16 rows) ====
__global__ void __launch_bounds__(256) k_agg1(const float* __restrict__ b1) {
    int wg = (blockIdx.x * blockDim.x + threadIdx.x) >> 5;
    if (wg >= NN) return;
    const int d = wg;
    const int lane = threadIdx.x & 31;

    const __half2* hs2 = reinterpret_cast<const __half2*>(g_hs);
    float2 acc = __half22float2(hs2[(size_t)d * 32 + lane]);

    const int beg = g_off[d];
    const int cnt = g_indeg[d];
    for (int base = 0; base < cnt; base += 32) {
        int rem = cnt - base;
        int take = rem < 32 ? rem : 32;
        int s = 0;
        if (lane < take) s = g_csrc[beg + base + lane];
#pragma unroll 8
        for (int j = 0; j < take; j++) {
            int sj = __shfl_sync(0xffffffffu, s, j);
            float2 v = __half22float2(hs2[(size_t)sj * 32 + lane]);
            acc.x += v.x;
            acc.y += v.y;
        }
    }

    float di = g_dinv[d];
    float2 b = reinterpret_cast<const float2*>(b1)[lane];
    float2 o;
    o.x = fmaxf(fmaf(acc.x, di, b.x), 0.0f);
    o.y = fmaxf(fmaf(acc.y, di, b.y), 0.0f);
    reinterpret_cast<float2*>(g_agg)[(size_t)d * 32 + lane] = o;
}

// ========== GEMM2: h2s = half((agg @ W2) * dinv[row]), fp16 stride-16 ==========
__global__ void __launch_bounds__(256) k_gemm2(const float* __restrict__ W2) {
    __shared__ float Ws[FH * FO];
    for (int i = threadIdx.x; i < FH * FO; i += blockDim.x) Ws[i] = W2[i];
    __syncthreads();

    int n = blockIdx.x * blockDim.x + threadIdx.x;
    if (n >= NN) return;

    float acc[FO];
#pragma unroll
    for (int j = 0; j < FO; j++) acc[j] = 0.0f;

    const float4* a4 = reinterpret_cast<const float4*>(g_agg + (size_t)n * FH);
#pragma unroll
    for (int k4 = 0; k4 < 16; k4++) {
        float4 a = a4[k4];
        float av[4] = {a.x, a.y, a.z, a.w};
#pragma unroll
        for (int kk = 0; kk < 4; kk++) {
            int k = k4 * 4 + kk;
#pragma unroll
            for (int j = 0; j < FO; j++) acc[j] = fmaf(av[kk], Ws[k * FO + j], acc[j]);
        }
    }

    float di = g_dinv[n];
    unsigned* o2 = reinterpret_cast<unsigned*>(g_h2s + (size_t)n * 16);
#pragma unroll
    for (int p = 0; p < 5; p++) {
        __half2 h = __float22half2_rn(make_float2(acc[p * 2] * di, acc[p * 2 + 1] * di));
        o2[p] = h2_bits(h);
    }
}

// ===== agg2: warp-per-node gather (shfl indices, fp16 rows, 5 active lanes) =====
__global__ void __launch_bounds__(256) k_agg2(const float* __restrict__ b2,
                                              float* __restrict__ out) {
    int wg = (blockIdx.x * blockDim.x + threadIdx.x) >> 5;
    if (wg >= NN) return;
    const int d = wg;
    const int lane = threadIdx.x & 31;

    const __half2* h2p = reinterpret_cast<const __half2*>(g_h2s);
    float2 acc = make_float2(0.f, 0.f);
    if (lane < 5) acc = __half22float2(h2p[(size_t)d * 8 + lane]);

    const int beg = g_off[d];
    const int cnt = g_indeg[d];
    for (int base = 0; base < cnt; base += 32) {
        int rem = cnt - base;
        int take = rem < 32 ? rem : 32;
        int s = 0;
        if (lane < take) s = g_csrc[beg + base + lane];
#pragma unroll 8
        for (int j = 0; j < take; j++) {
            int sj = __shfl_sync(0xffffffffu, s, j);
            if (lane < 5) {
                float2 v = __half22float2(h2p[(size_t)sj * 8 + lane]);
                acc.x += v.x;
                acc.y += v.y;
            }
        }
    }

    if (lane < 5) {
        float di = g_dinv[d];
        float* op = out + (size_t)d * FO;
        op[lane * 2]     = fmaf(acc.x, di, b2[lane * 2]);
        op[lane * 2 + 1] = fmaf(acc.y, di, b2[lane * 2 + 1]);
    }
}

extern "C" void kernel_launch(void* const* d_in, const int* in_sizes, int n_in,
                              void* d_out, int out_size) {
    const float* x  = (const float*)d_in[0];
    const int*   ei = (const int*)d_in[1];
    const float* W1 = (const float*)d_in[2];
    const float* b1 = (const float*)d_in[3];
    const float* W2 = (const float*)d_in[4];
    const float* b2 = (const float*)d_in[5];
    float* out = (float*)d_out;

    const int* src = ei;
    const int* dst = ei + NE;

    static bool attr_set = false;
    if (!attr_set) {
        cudaFuncSetAttribute(k_gemm1, cudaFuncAttributeMaxDynamicSharedMemorySize,
                             GEMM1_SMEM);
        attr_set = true;
    }

    k_zero<<<(NN + 255) / 256, 256>>>();
    k_indeg<<<(NE + 255) / 256, 256>>>(dst);
    k_scan1<<<NSCAN, SCAN_BLK>>>();
    k_scan_apply<<<(NN + 255) / 256, 256>>>();
    k_edge_pos<<<(NE + 255) / 256, 256>>>(src, dst);
    k_gemm1<<<(NN + 255) / 256, 256, GEMM1_SMEM>>>(x, W1);
    k_agg1<<<(NN * 32 + 255) / 256, 256>>>(b1);
    k_gemm2<<<(NN + 255) / 256, 256>>>(W2);
    k_agg2<<<(NN * 32 + 255) / 256, 256>>>(b2, out);
}

// round 8
// speedup vs baseline: 1.2648x; 1.0710x over previous
#include <cuda_runtime.h>
#include <cuda_fp16.h>

#define NN 100000
#define NE 1600000
#define FIN 128
#define FH  64
#define FO  10

#define SCAN_BLK 512
#define NSCAN ((NN + SCAN_BLK - 1) / SCAN_BLK)   // 196

typedef unsigned long long u64;

// ---- scratch (device globals; no allocation allowed) ----
__device__ int   g_indeg[NN];
__device__ int   g_off[NN];
__device__ int   g_cursor[NN];
__device__ int   g_offp[NN];
__device__ int   g_bsum[NSCAN];
__device__ int   g_csrc[NE];
__device__ float g_dinv[NN];
__device__ __align__(16) __half g_hs[NN * FH];   // (x@W1) * dinv[row], fp16
__device__ __align__(16) float  g_agg[NN * FH];  // relu(b1 + dinv*(hs[d]+sum hs[src]))
__device__ __align__(16) __half g_h2s[NN * 16];  // (agg@W2) * dinv[row], fp16, stride 16

// ---- packed f32x2 helpers ----
__device__ __forceinline__ u64 dup2(float v) {
    u64 d; asm("mov.b64 %0, {%1,%1};" : "=l"(d) : "f"(v)); return d;
}
__device__ __forceinline__ void ffma2(u64& d, u64 a, u64 b) {
    asm("fma.rn.f32x2 %0, %1, %2, %0;" : "+l"(d) : "l"(a), "l"(b));
}
__device__ __forceinline__ float2 unpack2(u64 d) {
    float lo, hi; asm("mov.b64 {%0,%1}, %2;" : "=f"(lo), "=f"(hi) : "l"(d));
    return make_float2(lo, hi);
}
__device__ __forceinline__ unsigned h2_bits(__half2 h) {
    return *reinterpret_cast<unsigned*>(&h);
}

// ================= degree =================
__global__ void k_indeg(const int* __restrict__ dst) {
    int e = blockIdx.x * blockDim.x + threadIdx.x;
    if (e < NE) atomicAdd(&g_indeg[dst[e]], 1);
}

// ================= scan pass 1 (+ dinv fused) =================
__global__ void __launch_bounds__(SCAN_BLK) k_scan1() {
    int i = blockIdx.x * SCAN_BLK + threadIdx.x;
    int v = (i < NN) ? g_indeg[i] : 0;
    if (i < NN) g_dinv[i] = rsqrtf(1.0f + (float)v);
    int lane = threadIdx.x & 31, w = threadIdx.x >> 5;
    int s = v;
#pragma unroll
    for (int o = 1; o < 32; o <<= 1) {
        int t = __shfl_up_sync(0xffffffffu, s, o);
        if (lane >= o) s += t;
    }
    __shared__ int wsum[16];
    if (lane == 31) wsum[w] = s;
    __syncthreads();
    if (w == 0) {
        int t = (lane < 16) ? wsum[lane] : 0;
#pragma unroll
        for (int o = 1; o < 16; o <<= 1) {
            int u = __shfl_up_sync(0xffffffffu, t, o);
            if (lane >= o) t += u;
        }
        if (lane < 16) wsum[lane] = t;
    }
    __syncthreads();
    int excl = s - v + ((w > 0) ? wsum[w - 1] : 0);
    if (i < NN) g_offp[i] = excl;
    if (threadIdx.x == 0) g_bsum[blockIdx.x] = wsum[15];
}

// ===== scan pass 2 fused into apply: every block scans the 196 block sums =====
__global__ void __launch_bounds__(256) k_scan_apply() {
    __shared__ int s_ex[256];
    int tid = threadIdx.x;
    {
        int v = (tid < NSCAN) ? g_bsum[tid] : 0;
        int lane = tid & 31, w = tid >> 5;
        int s = v;
#pragma unroll
        for (int o = 1; o < 32; o <<= 1) {
            int t = __shfl_up_sync(0xffffffffu, s, o);
            if (lane >= o) s += t;
        }
        __shared__ int wsum[8];
        if (lane == 31) wsum[w] = s;
        __syncthreads();
        if (w == 0) {
            int t = (lane < 8) ? wsum[lane] : 0;
#pragma unroll
            for (int o = 1; o < 8; o <<= 1) {
                int u = __shfl_up_sync(0xffffffffu, t, o);
                if (lane >= o) t += u;
            }
            if (lane < 8) wsum[lane] = t;
        }
        __syncthreads();
        s_ex[tid] = s - v + ((w > 0) ? wsum[w - 1] : 0);  // exclusive
        __syncthreads();
    }
    int i = blockIdx.x * 256 + tid;
    if (i < NN) {
        int o = g_offp[i] + s_ex[i >> 9];
        g_off[i] = o;
        g_cursor[i] = o;
    }
}

// ================= CSR positional scatter =================
__global__ void k_edge_pos(const int* __restrict__ src, const int* __restrict__ dst) {
    int e = blockIdx.x * blockDim.x + threadIdx.x;
    if (e < NE) {
        int pos = atomicAdd(&g_cursor[dst[e]], 1);
        g_csrc[pos] = src[e];
    }
}

// ================= GEMM1: hs = half(x @ W1 * dinv[row]) =================
#define XS_F4 (256 * 17)
#define GEMM1_SMEM (XS_F4 * 16 + 64 * 64 * 4)   // 86016 B

__global__ void __launch_bounds__(256, 2) k_gemm1(const float* __restrict__ x,
                                                  const float* __restrict__ W1) {
    extern __shared__ float4 sm4[];
    float4* xs4 = sm4;                     // [256][17]
    float*  Ws  = (float*)(sm4 + XS_F4);   // [64][64]

    const int tid = threadIdx.x;
    const int c  = tid & 7;
    const int rg = tid >> 3;
    const int row_base = blockIdx.x * 256;

    u64 acc[8][4];
#pragma unroll
    for (int i = 0; i < 8; i++)
#pragma unroll
        for (int p = 0; p < 4; p++) acc[i][p] = 0ull;

    const float4* x4  = reinterpret_cast<const float4*>(x);
    const float4* W14 = reinterpret_cast<const float4*>(W1);
    float4* Ws4 = reinterpret_cast<float4*>(Ws);

    for (int kc = 0; kc < 2; kc++) {
#pragma unroll
        for (int j = 0; j < 16; j++) {
            int f = tid + 256 * j;
            int row = f >> 4;
            int kq  = f & 15;
            int grow = min(row_base + row, NN - 1);
            xs4[row * 17 + kq] = x4[(size_t)grow * 32 + kc * 16 + kq];
        }
#pragma unroll
        for (int j = 0; j < 4; j++) {
            int f = tid + 256 * j;
            Ws4[f] = W14[kc * 1024 + f];
        }
        __syncthreads();

#define ROWSTEP(i, comp)                                   \
        {                                                  \
            u64 xd = dup2(xq[i].comp);                     \
            ffma2(acc[i][0], xd, wA.x);                    \
            ffma2(acc[i][1], xd, wA.y);                    \
            ffma2(acc[i][2], xd, wB.x);                    \
            ffma2(acc[i][3], xd, wB.y);                    \
        }
#define KSTEP(comp, kk)                                                        \
        {                                                                      \
            const ulonglong2* wr =                                             \
                (const ulonglong2*)(Ws + (k4 * 4 + kk) * 64 + c * 8);          \
            ulonglong2 wA = wr[0];                                             \
            ulonglong2 wB = wr[1];                                             \
            ROWSTEP(0, comp) ROWSTEP(1, comp) ROWSTEP(2, comp) ROWSTEP(3, comp)\
            ROWSTEP(4, comp) ROWSTEP(5, comp) ROWSTEP(6, comp) ROWSTEP(7, comp)\
        }

#pragma unroll 4
        for (int k4 = 0; k4 < 16; k4++) {
            float4 xq[8];
#pragma unroll
            for (int i = 0; i < 8; i++) xq[i] = xs4[(rg + 32 * i) * 17 + k4];
            KSTEP(x, 0)
            KSTEP(y, 1)
            KSTEP(z, 2)
            KSTEP(w, 3)
        }
        __syncthreads();
    }

    uint4* hs16 = reinterpret_cast<uint4*>(g_hs);
#pragma unroll
    for (int i = 0; i < 8; i++) {
        int grow = row_base + rg + 32 * i;
        if (grow < NN) {
            float di = g_dinv[grow];
            float2 p0 = unpack2(acc[i][0]);
            float2 p1 = unpack2(acc[i][1]);
            float2 p2 = unpack2(acc[i][2]);
            float2 p3 = unpack2(acc[i][3]);
            __half2 h0 = __float22half2_rn(make_float2(p0.x * di, p0.y * di));
            __half2 h1 = __float22half2_rn(make_float2(p1.x * di, p1.y * di));
            __half2 h2 = __float22half2_rn(make_float2(p2.x * di, p2.y * di));
            __half2 h3 = __float22half2_rn(make_float2(p3.x * di, p3.y * di));
            uint4 u;
            u.x = h2_bits(h0);
            u.y = h2_bits(h1);
            u.z = h2_bits(h2);
            u.w = h2_bits(h3);
            hs16[(size_t)grow * 8 + c] = u;
        }
    }
#undef KSTEP
#undef ROWSTEP
}

// ================= agg1: warp-per-node gather-sum (shfl indices, fp16 rows) ====
__global__ void __launch_bounds__(256) k_agg1(const float* __restrict__ b1) {
    int wg = (blockIdx.x * blockDim.x + threadIdx.x) >> 5;
    if (wg >= NN) return;
    const int d = wg;
    const int lane = threadIdx.x & 31;

    const __half2* hs2 = reinterpret_cast<const __half2*>(g_hs);
    float2 acc = __half22float2(hs2[(size_t)d * 32 + lane]);

    const int beg = g_off[d];
    const int cnt = g_indeg[d];
    for (int base = 0; base < cnt; base += 32) {
        int rem = cnt - base;
        int take = rem < 32 ? rem : 32;
        int s = 0;
        if (lane < take) s = g_csrc[beg + base + lane];
#pragma unroll 8
        for (int j = 0; j < take; j++) {
            int sj = __shfl_sync(0xffffffffu, s, j);
            float2 v = __half22float2(hs2[(size_t)sj * 32 + lane]);
            acc.x += v.x;
            acc.y += v.y;
        }
    }

    float di = g_dinv[d];
    float2 b = reinterpret_cast<const float2*>(b1)[lane];
    float2 o;
    o.x = fmaxf(fmaf(acc.x, di, b.x), 0.0f);
    o.y = fmaxf(fmaf(acc.y, di, b.y), 0.0f);
    reinterpret_cast<float2*>(g_agg)[(size_t)d * 32 + lane] = o;
}

// ========== GEMM2: h2s = half((agg @ W2) * dinv[row]), fp16 stride-16 ==========
__global__ void __launch_bounds__(256) k_gemm2(const float* __restrict__ W2) {
    __shared__ float Ws[FH * FO];
    for (int i = threadIdx.x; i < FH * FO; i += blockDim.x) Ws[i] = W2[i];
    __syncthreads();

    int n = blockIdx.x * blockDim.x + threadIdx.x;
    if (n >= NN) return;

    float acc[FO];
#pragma unroll
    for (int j = 0; j < FO; j++) acc[j] = 0.0f;

    const float4* a4 = reinterpret_cast<const float4*>(g_agg + (size_t)n * FH);
#pragma unroll
    for (int k4 = 0; k4 < 16; k4++) {
        float4 a = a4[k4];
        float av[4] = {a.x, a.y, a.z, a.w};
#pragma unroll
        for (int kk = 0; kk < 4; kk++) {
            int k = k4 * 4 + kk;
#pragma unroll
            for (int j = 0; j < FO; j++) acc[j] = fmaf(av[kk], Ws[k * FO + j], acc[j]);
        }
    }

    float di = g_dinv[n];
    unsigned* o2 = reinterpret_cast<unsigned*>(g_h2s + (size_t)n * 16);
#pragma unroll
    for (int p = 0; p < 5; p++) {
        __half2 h = __float22half2_rn(make_float2(acc[p * 2] * di, acc[p * 2 + 1] * di));
        o2[p] = h2_bits(h);
    }
}

// ===== agg2: warp-per-node gather (shfl indices, fp16 rows, 5 active lanes) =====
__global__ void __launch_bounds__(256) k_agg2(const float* __restrict__ b2,
                                              float* __restrict__ out) {
    int wg = (blockIdx.x * blockDim.x + threadIdx.x) >> 5;
    if (wg >= NN) return;
    const int d = wg;
    const int lane = threadIdx.x & 31;

    const __half2* h2p = reinterpret_cast<const __half2*>(g_h2s);
    float2 acc = make_float2(0.f, 0.f);
    if (lane < 5) acc = __half22float2(h2p[(size_t)d * 8 + lane]);

    const int beg = g_off[d];
    const int cnt = g_indeg[d];
    for (int base = 0; base < cnt; base += 32) {
        int rem = cnt - base;
        int take = rem < 32 ? rem : 32;
        int s = 0;
        if (lane < take) s = g_csrc[beg + base + lane];
#pragma unroll 8
        for (int j = 0; j < take; j++) {
            int sj = __shfl_sync(0xffffffffu, s, j);
            if (lane < 5) {
                float2 v = __half22float2(h2p[(size_t)sj * 8 + lane]);
                acc.x += v.x;
                acc.y += v.y;
            }
        }
    }

    if (lane < 5) {
        float di = g_dinv[d];
        float* op = out + (size_t)d * FO;
        op[lane * 2]     = fmaf(acc.x, di, b2[lane * 2]);
        op[lane * 2 + 1] = fmaf(acc.y, di, b2[lane * 2 + 1]);
    }
}

extern "C" void kernel_launch(void* const* d_in, const int* in_sizes, int n_in,
                              void* d_out, int out_size) {
    const float* x  = (const float*)d_in[0];
    const int*   ei = (const int*)d_in[1];
    const float* W1 = (const float*)d_in[2];
    const float* b1 = (const float*)d_in[3];
    const float* W2 = (const float*)d_in[4];
    const float* b2 = (const float*)d_in[5];
    float* out = (float*)d_out;

    const int* src = ei;
    const int* dst = ei + NE;

    static bool init_done = false;
    static cudaStream_t s2;
    static cudaEvent_t ev_fork, ev_join;
    static void* indeg_ptr = nullptr;
    if (!init_done) {
        cudaFuncSetAttribute(k_gemm1, cudaFuncAttributeMaxDynamicSharedMemorySize,
                             GEMM1_SMEM);
        cudaStreamCreateWithFlags(&s2, cudaStreamNonBlocking);
        cudaEventCreateWithFlags(&ev_fork, cudaEventDisableTiming);
        cudaEventCreateWithFlags(&ev_join, cudaEventDisableTiming);
        cudaGetSymbolAddress(&indeg_ptr, g_indeg);
        init_done = true;
    }

    // ---- serial prefix on capture stream: indeg + dinv ----
    cudaMemsetAsync(indeg_ptr, 0, NN * sizeof(int), 0);
    k_indeg<<<(NE + 255) / 256, 256>>>(dst);
    k_scan1<<<NSCAN, SCAN_BLK>>>();

    // ---- fork: gemm1 (needs only dinv) runs concurrently with CSR build ----
    cudaEventRecord(ev_fork, 0);
    cudaStreamWaitEvent(s2, ev_fork, 0);
    k_gemm1<<<(NN + 255) / 256, 256, GEMM1_SMEM, s2>>>(x, W1);

    k_scan_apply<<<(NN + 255) / 256, 256>>>();
    k_edge_pos<<<(NE + 255) / 256, 256>>>(src, dst);

    // ---- join ----
    cudaEventRecord(ev_join, s2);
    cudaStreamWaitEvent(0, ev_join, 0);

    k_agg1<<<(NN * 32 + 255) / 256, 256>>>(b1);
    k_gemm2<<<(NN + 255) / 256, 256>>>(W2);
    k_agg2<<<(NN * 32 + 255) / 256, 256>>>(b2, out);
}

// round 9
// speedup vs baseline: 1.2733x; 1.0067x over previous
#include <cuda_runtime.h>
#include <cuda_fp16.h>

#define NN 100000
#define NE 1600000
#define FIN 128
#define FH  64
#define FO  10

#define SCAN_BLK 512
#define NSCAN ((NN + SCAN_BLK - 1) / SCAN_BLK)   // 196

typedef unsigned long long u64;

// ---- scratch (device globals; no allocation allowed) ----
__device__ int   g_indeg[NN];
__device__ int   g_off[NN];
__device__ int   g_cursor[NN];
__device__ int   g_offp[NN];
__device__ int   g_bsum[NSCAN];
__device__ int   g_csrc[NE];
__device__ float g_dinv[NN];
__device__ __align__(16) __half g_hs[NN * FH];   // x@W1 (unscaled, then *= dinv)
__device__ __align__(16) float  g_agg[NN * FH];  // relu(b1 + dinv*(hs[d]+sum hs[src]))
__device__ __align__(16) __half g_h2s[NN * 16];  // (agg@W2) * dinv[row], fp16, stride 16

// ---- packed f32x2 helpers ----
__device__ __forceinline__ u64 dup2(float v) {
    u64 d; asm("mov.b64 %0, {%1,%1};" : "=l"(d) : "f"(v)); return d;
}
__device__ __forceinline__ void ffma2(u64& d, u64 a, u64 b) {
    asm("fma.rn.f32x2 %0, %1, %2, %0;" : "+l"(d) : "l"(a), "l"(b));
}
__device__ __forceinline__ float2 unpack2(u64 d) {
    float lo, hi; asm("mov.b64 {%0,%1}, %2;" : "=f"(lo), "=f"(hi) : "l"(d));
    return make_float2(lo, hi);
}
__device__ __forceinline__ unsigned h2_bits(__half2 h) {
    return *reinterpret_cast<unsigned*>(&h);
}

// ================= degree =================
__global__ void k_indeg(const int* __restrict__ dst) {
    int e = blockIdx.x * blockDim.x + threadIdx.x;
    if (e < NE) atomicAdd(&g_indeg[dst[e]], 1);
}

// ================= scan pass 1 (+ dinv fused) =================
__global__ void __launch_bounds__(SCAN_BLK) k_scan1() {
    int i = blockIdx.x * SCAN_BLK + threadIdx.x;
    int v = (i < NN) ? g_indeg[i] : 0;
    if (i < NN) g_dinv[i] = rsqrtf(1.0f + (float)v);
    int lane = threadIdx.x & 31, w = threadIdx.x >> 5;
    int s = v;
#pragma unroll
    for (int o = 1; o < 32; o <<= 1) {
        int t = __shfl_up_sync(0xffffffffu, s, o);
        if (lane >= o) s += t;
    }
    __shared__ int wsum[16];
    if (lane == 31) wsum[w] = s;
    __syncthreads();
    if (w == 0) {
        int t = (lane < 16) ? wsum[lane] : 0;
#pragma unroll
        for (int o = 1; o < 16; o <<= 1) {
            int u = __shfl_up_sync(0xffffffffu, t, o);
            if (lane >= o) t += u;
        }
        if (lane < 16) wsum[lane] = t;
    }
    __syncthreads();
    int excl = s - v + ((w > 0) ? wsum[w - 1] : 0);
    if (i < NN) g_offp[i] = excl;
    if (threadIdx.x == 0) g_bsum[blockIdx.x] = wsum[15];
}

// ===== scan pass 2 fused into apply: every block scans the 196 block sums =====
__global__ void __launch_bounds__(256) k_scan_apply() {
    __shared__ int s_ex[256];
    int tid = threadIdx.x;
    {
        int v = (tid < NSCAN) ? g_bsum[tid] : 0;
        int lane = tid & 31, w = tid >> 5;
        int s = v;
#pragma unroll
        for (int o = 1; o < 32; o <<= 1) {
            int t = __shfl_up_sync(0xffffffffu, s, o);
            if (lane >= o) s += t;
        }
        __shared__ int wsum[8];
        if (lane == 31) wsum[w] = s;
        __syncthreads();
        if (w == 0) {
            int t = (lane < 8) ? wsum[lane] : 0;
#pragma unroll
            for (int o = 1; o < 8; o <<= 1) {
                int u = __shfl_up_sync(0xffffffffu, t, o);
                if (lane >= o) t += u;
            }
            if (lane < 8) wsum[lane] = t;
        }
        __syncthreads();
        s_ex[tid] = s - v + ((w > 0) ? wsum[w - 1] : 0);  // exclusive
        __syncthreads();
    }
    int i = blockIdx.x * 256 + tid;
    if (i < NN) {
        int o = g_offp[i] + s_ex[i >> 9];
        g_off[i] = o;
        g_cursor[i] = o;
    }
}

// ================= CSR positional scatter =================
__global__ void k_edge_pos(const int* __restrict__ src, const int* __restrict__ dst) {
    int e = blockIdx.x * blockDim.x + threadIdx.x;
    if (e < NE) {
        int pos = atomicAdd(&g_cursor[dst[e]], 1);
        g_csrc[pos] = src[e];
    }
}

// ================= GEMM1: hs = half(x @ W1)  (unscaled; no deps) =============
#define XS_F4 (256 * 17)
#define GEMM1_SMEM (XS_F4 * 16 + 64 * 64 * 4)   // 86016 B

__global__ void __launch_bounds__(256, 2) k_gemm1(const float* __restrict__ x,
                                                  const float* __restrict__ W1) {
    extern __shared__ float4 sm4[];
    float4* xs4 = sm4;                     // [256][17]
    float*  Ws  = (float*)(sm4 + XS_F4);   // [64][64]

    const int tid = threadIdx.x;
    const int c  = tid & 7;
    const int rg = tid >> 3;
    const int row_base = blockIdx.x * 256;

    u64 acc[8][4];
#pragma unroll
    for (int i = 0; i < 8; i++)
#pragma unroll
        for (int p = 0; p < 4; p++) acc[i][p] = 0ull;

    const float4* x4  = reinterpret_cast<const float4*>(x);
    const float4* W14 = reinterpret_cast<const float4*>(W1);
    float4* Ws4 = reinterpret_cast<float4*>(Ws);

    for (int kc = 0; kc < 2; kc++) {
#pragma unroll
        for (int j = 0; j < 16; j++) {
            int f = tid + 256 * j;
            int row = f >> 4;
            int kq  = f & 15;
            int grow = min(row_base + row, NN - 1);
            xs4[row * 17 + kq] = x4[(size_t)grow * 32 + kc * 16 + kq];
        }
#pragma unroll
        for (int j = 0; j < 4; j++) {
            int f = tid + 256 * j;
            Ws4[f] = W14[kc * 1024 + f];
        }
        __syncthreads();

#define ROWSTEP(i, comp)                                   \
        {                                                  \
            u64 xd = dup2(xq[i].comp);                     \
            ffma2(acc[i][0], xd, wA.x);                    \
            ffma2(acc[i][1], xd, wA.y);                    \
            ffma2(acc[i][2], xd, wB.x);                    \
            ffma2(acc[i][3], xd, wB.y);                    \
        }
#define KSTEP(comp, kk)                                                        \
        {                                                                      \
            const ulonglong2* wr =                                             \
                (const ulonglong2*)(Ws + (k4 * 4 + kk) * 64 + c * 8);          \
            ulonglong2 wA = wr[0];                                             \
            ulonglong2 wB = wr[1];                                             \
            ROWSTEP(0, comp) ROWSTEP(1, comp) ROWSTEP(2, comp) ROWSTEP(3, comp)\
            ROWSTEP(4, comp) ROWSTEP(5, comp) ROWSTEP(6, comp) ROWSTEP(7, comp)\
        }

#pragma unroll 4
        for (int k4 = 0; k4 < 16; k4++) {
            float4 xq[8];
#pragma unroll
            for (int i = 0; i < 8; i++) xq[i] = xs4[(rg + 32 * i) * 17 + k4];
            KSTEP(x, 0)
            KSTEP(y, 1)
            KSTEP(z, 2)
            KSTEP(w, 3)
        }
        __syncthreads();
    }

    uint4* hs16 = reinterpret_cast<uint4*>(g_hs);
#pragma unroll
    for (int i = 0; i < 8; i++) {
        int grow = row_base + rg + 32 * i;
        if (grow < NN) {
            float2 p0 = unpack2(acc[i][0]);
            float2 p1 = unpack2(acc[i][1]);
            float2 p2 = unpack2(acc[i][2]);
            float2 p3 = unpack2(acc[i][3]);
            __half2 h0 = __float22half2_rn(p0);
            __half2 h1 = __float22half2_rn(p1);
            __half2 h2 = __float22half2_rn(p2);
            __half2 h3 = __float22half2_rn(p3);
            uint4 u;
            u.x = h2_bits(h0);
            u.y = h2_bits(h1);
            u.z = h2_bits(h2);
            u.w = h2_bits(h3);
            hs16[(size_t)grow * 8 + c] = u;
        }
    }
#undef KSTEP
#undef ROWSTEP
}

// ================= scale: hs[n][:] *= dinv[n]  (after join) =================
__global__ void __launch_bounds__(256) k_scale() {
    int idx = blockIdx.x * blockDim.x + threadIdx.x;  // over NN*8 uint4
    if (idx >= NN * 8) return;
    int n = idx >> 3;
    float di = g_dinv[n];
    uint4* hs16 = reinterpret_cast<uint4*>(g_hs);
    uint4 u = hs16[idx];
    unsigned* up = &u.x;
#pragma unroll
    for (int p = 0; p < 4; p++) {
        __half2 h = *reinterpret_cast<__half2*>(&up[p]);
        float2 f = __half22float2(h);
        f.x *= di; f.y *= di;
        __half2 r = __float22half2_rn(f);
        up[p] = h2_bits(r);
    }
    hs16[idx] = u;
}

// ================= agg1: warp-per-node gather-sum (shfl indices, fp16 rows) ====
__global__ void __launch_bounds__(256) k_agg1(const float* __restrict__ b1) {
    int wg = (blockIdx.x * blockDim.x + threadIdx.x) >> 5;
    if (wg >= NN) return;
    const int d = wg;
    const int lane = threadIdx.x & 31;

    const __half2* hs2 = reinterpret_cast<const __half2*>(g_hs);
    float2 acc = __half22float2(hs2[(size_t)d * 32 + lane]);

    const int beg = g_off[d];
    const int cnt = g_indeg[d];
    for (int base = 0; base < cnt; base += 32) {
        int rem = cnt - base;
        int take = rem < 32 ? rem : 32;
        int s = 0;
        if (lane < take) s = g_csrc[beg + base + lane];
#pragma unroll 8
        for (int j = 0; j < take; j++) {
            int sj = __shfl_sync(0xffffffffu, s, j);
            float2 v = __half22float2(hs2[(size_t)sj * 32 + lane]);
            acc.x += v.x;
            acc.y += v.y;
        }
    }

    float di = g_dinv[d];
    float2 b = reinterpret_cast<const float2*>(b1)[lane];
    float2 o;
    o.x = fmaxf(fmaf(acc.x, di, b.x), 0.0f);
    o.y = fmaxf(fmaf(acc.y, di, b.y), 0.0f);
    reinterpret_cast<float2*>(g_agg)[(size_t)d * 32 + lane] = o;
}

// ========== GEMM2: h2s = half((agg @ W2) * dinv[row]), fp16 stride-16 ==========
__global__ void __launch_bounds__(256) k_gemm2(const float* __restrict__ W2) {
    __shared__ float Ws[FH * FO];
    for (int i = threadIdx.x; i < FH * FO; i += blockDim.x) Ws[i] = W2[i];
    __syncthreads();

    int n = blockIdx.x * blockDim.x + threadIdx.x;
    if (n >= NN) return;

    float acc[FO];
#pragma unroll
    for (int j = 0; j < FO; j++) acc[j] = 0.0f;

    const float4* a4 = reinterpret_cast<const float4*>(g_agg + (size_t)n * FH);
#pragma unroll
    for (int k4 = 0; k4 < 16; k4++) {
        float4 a = a4[k4];
        float av[4] = {a.x, a.y, a.z, a.w};
#pragma unroll
        for (int kk = 0; kk < 4; kk++) {
            int k = k4 * 4 + kk;
#pragma unroll
            for (int j = 0; j < FO; j++) acc[j] = fmaf(av[kk], Ws[k * FO + j], acc[j]);
        }
    }

    float di = g_dinv[n];
    unsigned* o2 = reinterpret_cast<unsigned*>(g_h2s + (size_t)n * 16);
#pragma unroll
    for (int p = 0; p < 5; p++) {
        __half2 h = __float22half2_rn(make_float2(acc[p * 2] * di, acc[p * 2 + 1] * di));
        o2[p] = h2_bits(h);
    }
}

// ===== agg2: warp-per-node gather (shfl indices, fp16 rows, 5 active lanes) =====
__global__ void __launch_bounds__(256) k_agg2(const float* __restrict__ b2,
                                              float* __restrict__ out) {
    int wg = (blockIdx.x * blockDim.x + threadIdx.x) >> 5;
    if (wg >= NN) return;
    const int d = wg;
    const int lane = threadIdx.x & 31;

    const __half2* h2p = reinterpret_cast<const __half2*>(g_h2s);
    float2 acc = make_float2(0.f, 0.f);
    if (lane < 5) acc = __half22float2(h2p[(size_t)d * 8 + lane]);

    const int beg = g_off[d];
    const int cnt = g_indeg[d];
    for (int base = 0; base < cnt; base += 32) {
        int rem = cnt - base;
        int take = rem < 32 ? rem : 32;
        int s = 0;
        if (lane < take) s = g_csrc[beg + base + lane];
#pragma unroll 8
        for (int j = 0; j < take; j++) {
            int sj = __shfl_sync(0xffffffffu, s, j);
            if (lane < 5) {
                float2 v = __half22float2(h2p[(size_t)sj * 8 + lane]);
                acc.x += v.x;
                acc.y += v.y;
            }
        }
    }

    if (lane < 5) {
        float di = g_dinv[d];
        float* op = out + (size_t)d * FO;
        op[lane * 2]     = fmaf(acc.x, di, b2[lane * 2]);
        op[lane * 2 + 1] = fmaf(acc.y, di, b2[lane * 2 + 1]);
    }
}

extern "C" void kernel_launch(void* const* d_in, const int* in_sizes, int n_in,
                              void* d_out, int out_size) {
    const float* x  = (const float*)d_in[0];
    const int*   ei = (const int*)d_in[1];
    const float* W1 = (const float*)d_in[2];
    const float* b1 = (const float*)d_in[3];
    const float* W2 = (const float*)d_in[4];
    const float* b2 = (const float*)d_in[5];
    float* out = (float*)d_out;

    const int* src = ei;
    const int* dst = ei + NE;

    static bool init_done = false;
    static cudaStream_t s2;
    static cudaEvent_t ev_fork, ev_join;
    static void* indeg_ptr = nullptr;
    if (!init_done) {
        cudaFuncSetAttribute(k_gemm1, cudaFuncAttributeMaxDynamicSharedMemorySize,
                             GEMM1_SMEM);
        cudaStreamCreateWithFlags(&s2, cudaStreamNonBlocking);
        cudaEventCreateWithFlags(&ev_fork, cudaEventDisableTiming);
        cudaEventCreateWithFlags(&ev_join, cudaEventDisableTiming);
        cudaGetSymbolAddress(&indeg_ptr, g_indeg);
        init_done = true;
    }

    // ---- fork immediately: gemm1 has no input deps now ----
    cudaEventRecord(ev_fork, 0);
    cudaStreamWaitEvent(s2, ev_fork, 0);
    k_gemm1<<<(NN + 255) / 256, 256, GEMM1_SMEM, s2>>>(x, W1);

    // ---- full prepass on capture stream, concurrent with gemm1 ----
    cudaMemsetAsync(indeg_ptr, 0, NN * sizeof(int), 0);
    k_indeg<<<(NE + 255) / 256, 256>>>(dst);
    k_scan1<<<NSCAN, SCAN_BLK>>>();
    k_scan_apply<<<(NN + 255) / 256, 256>>>();
    k_edge_pos<<<(NE + 255) / 256, 256>>>(src, dst);

    // ---- join ----
    cudaEventRecord(ev_join, s2);
    cudaStreamWaitEvent(0, ev_join, 0);

    k_scale<<<(NN * 8 + 255) / 256, 256>>>();
    k_agg1<<<(NN * 32 + 255) / 256, 256>>>(b1);
    k_gemm2<<<(NN + 255) / 256, 256>>>(W2);
    k_agg2<<<(NN * 32 + 255) / 256, 256>>>(b2, out);
}

// round 10
// speedup vs baseline: 1.2971x; 1.0187x over previous
#include <cuda_runtime.h>
#include <cuda_fp16.h>

#define NN 100000
#define NE 1600000
#define FIN 128
#define FH  64
#define FO  10

#define SCAN_BLK 512
#define NSCAN ((NN + SCAN_BLK - 1) / SCAN_BLK)   // 196

typedef unsigned long long u64;

// ---- scratch (device globals; no allocation allowed) ----
__device__ int   g_indeg[NN];
__device__ int   g_off[NN];
__device__ int   g_cursor[NN];
__device__ int   g_offp[NN];
__device__ int   g_bsum[NSCAN];
__device__ int   g_csrc[NE];
__device__ float g_dinv[NN];
__device__ __align__(16) __half g_hs[NN * FH];   // x@W1 (unscaled, then *= dinv)
__device__ __align__(16) float  g_agg[NN * FH];  // relu(b1 + dinv*(hs[d]+sum hs[src]))
__device__ __align__(16) __half g_h2s[NN * 16];  // (agg@W2) * dinv[row], fp16, stride 16

// ---- packed f32x2 helpers ----
__device__ __forceinline__ u64 dup2(float v) {
    u64 d; asm("mov.b64 %0, {%1,%1};" : "=l"(d) : "f"(v)); return d;
}
__device__ __forceinline__ void ffma2(u64& d, u64 a, u64 b) {
    asm("fma.rn.f32x2 %0, %1, %2, %0;" : "+l"(d) : "l"(a), "l"(b));
}
__device__ __forceinline__ float2 unpack2(u64 d) {
    float lo, hi; asm("mov.b64 {%0,%1}, %2;" : "=f"(lo), "=f"(hi) : "l"(d));
    return make_float2(lo, hi);
}
__device__ __forceinline__ unsigned h2_bits(__half2 h) {
    return *reinterpret_cast<unsigned*>(&h);
}

// ================= degree =================
__global__ void k_indeg(const int* __restrict__ dst) {
    int e = blockIdx.x * blockDim.x + threadIdx.x;
    if (e < NE) atomicAdd(&g_indeg[dst[e]], 1);
}

// ================= scan pass 1 (+ dinv fused) =================
__global__ void __launch_bounds__(SCAN_BLK) k_scan1() {
    int i = blockIdx.x * SCAN_BLK + threadIdx.x;
    int v = (i < NN) ? g_indeg[i] : 0;
    if (i < NN) g_dinv[i] = rsqrtf(1.0f + (float)v);
    int lane = threadIdx.x & 31, w = threadIdx.x >> 5;
    int s = v;
#pragma unroll
    for (int o = 1; o < 32; o <<= 1) {
        int t = __shfl_up_sync(0xffffffffu, s, o);
        if (lane >= o) s += t;
    }
    __shared__ int wsum[16];
    if (lane == 31) wsum[w] = s;
    __syncthreads();
    if (w == 0) {
        int t = (lane < 16) ? wsum[lane] : 0;
#pragma unroll
        for (int o = 1; o < 16; o <<= 1) {
            int u = __shfl_up_sync(0xffffffffu, t, o);
            if (lane >= o) t += u;
        }
        if (lane < 16) wsum[lane] = t;
    }
    __syncthreads();
    int excl = s - v + ((w > 0) ? wsum[w - 1] : 0);
    if (i < NN) g_offp[i] = excl;
    if (threadIdx.x == 0) g_bsum[blockIdx.x] = wsum[15];
}

// ===== scan pass 2 fused into apply: every block scans the 196 block sums =====
__global__ void __launch_bounds__(256) k_scan_apply() {
    __shared__ int s_ex[256];
    int tid = threadIdx.x;
    {
        int v = (tid < NSCAN) ? g_bsum[tid] : 0;
        int lane = tid & 31, w = tid >> 5;
        int s = v;
#pragma unroll
        for (int o = 1; o < 32; o <<= 1) {
            int t = __shfl_up_sync(0xffffffffu, s, o);
            if (lane >= o) s += t;
        }
        __shared__ int wsum[8];
        if (lane == 31) wsum[w] = s;
        __syncthreads();
        if (w == 0) {
            int t = (lane < 8) ? wsum[lane] : 0;
#pragma unroll
            for (int o = 1; o < 8; o <<= 1) {
                int u = __shfl_up_sync(0xffffffffu, t, o);
                if (lane >= o) t += u;
            }
            if (lane < 8) wsum[lane] = t;
        }
        __syncthreads();
        s_ex[tid] = s - v + ((w > 0) ? wsum[w - 1] : 0);  // exclusive
        __syncthreads();
    }
    int i = blockIdx.x * 256 + tid;
    if (i < NN) {
        int o = g_offp[i] + s_ex[i >> 9];
        g_off[i] = o;
        g_cursor[i] = o;
    }
}

// ================= CSR positional scatter =================
__global__ void k_edge_pos(const int* __restrict__ src, const int* __restrict__ dst) {
    int e = blockIdx.x * blockDim.x + threadIdx.x;
    if (e < NE) {
        int pos = atomicAdd(&g_cursor[dst[e]], 1);
        g_csrc[pos] = src[e];
    }
}

// ================= GEMM1: hs = half(x @ W1)  (unscaled; no deps) =============
#define XS_F4 (256 * 17)
#define GEMM1_SMEM (XS_F4 * 16 + 64 * 64 * 4)   // 86016 B

__global__ void __launch_bounds__(256, 2) k_gemm1(const float* __restrict__ x,
                                                  const float* __restrict__ W1) {
    extern __shared__ float4 sm4[];
    float4* xs4 = sm4;                     // [256][17]
    float*  Ws  = (float*)(sm4 + XS_F4);   // [64][64]

    const int tid = threadIdx.x;
    const int c  = tid & 7;
    const int rg = tid >> 3;
    const int row_base = blockIdx.x * 256;

    u64 acc[8][4];
#pragma unroll
    for (int i = 0; i < 8; i++)
#pragma unroll
        for (int p = 0; p < 4; p++) acc[i][p] = 0ull;

    const float4* x4  = reinterpret_cast<const float4*>(x);
    const float4* W14 = reinterpret_cast<const float4*>(W1);
    float4* Ws4 = reinterpret_cast<float4*>(Ws);

    for (int kc = 0; kc < 2; kc++) {
#pragma unroll
        for (int j = 0; j < 16; j++) {
            int f = tid + 256 * j;
            int row = f >> 4;
            int kq  = f & 15;
            int grow = min(row_base + row, NN - 1);
            xs4[row * 17 + kq] = x4[(size_t)grow * 32 + kc * 16 + kq];
        }
#pragma unroll
        for (int j = 0; j < 4; j++) {
            int f = tid + 256 * j;
            Ws4[f] = W14[kc * 1024 + f];
        }
        __syncthreads();

#define ROWSTEP(i, comp)                                   \
        {                                                  \
            u64 xd = dup2(xq[i].comp);                     \
            ffma2(acc[i][0], xd, wA.x);                    \
            ffma2(acc[i][1], xd, wA.y);                    \
            ffma2(acc[i][2], xd, wB.x);                    \
            ffma2(acc[i][3], xd, wB.y);                    \
        }
#define KSTEP(comp, kk)                                                        \
        {                                                                      \
            const ulonglong2* wr =                                             \
                (const ulonglong2*)(Ws + (k4 * 4 + kk) * 64 + c * 8);          \
            ulonglong2 wA = wr[0];                                             \
            ulonglong2 wB = wr[1];                                             \
            ROWSTEP(0, comp) ROWSTEP(1, comp) ROWSTEP(2, comp) ROWSTEP(3, comp)\
            ROWSTEP(4, comp) ROWSTEP(5, comp) ROWSTEP(6, comp) ROWSTEP(7, comp)\
        }

#pragma unroll 4
        for (int k4 = 0; k4 < 16; k4++) {
            float4 xq[8];
#pragma unroll
            for (int i = 0; i < 8; i++) xq[i] = xs4[(rg + 32 * i) * 17 + k4];
            KSTEP(x, 0)
            KSTEP(y, 1)
            KSTEP(z, 2)
            KSTEP(w, 3)
        }
        __syncthreads();
    }

    uint4* hs16 = reinterpret_cast<uint4*>(g_hs);
#pragma unroll
    for (int i = 0; i < 8; i++) {
        int grow = row_base + rg + 32 * i;
        if (grow < NN) {
            float2 p0 = unpack2(acc[i][0]);
            float2 p1 = unpack2(acc[i][1]);
            float2 p2 = unpack2(acc[i][2]);
            float2 p3 = unpack2(acc[i][3]);
            uint4 u;
            u.x = h2_bits(__float22half2_rn(p0));
            u.y = h2_bits(__float22half2_rn(p1));
            u.z = h2_bits(__float22half2_rn(p2));
            u.w = h2_bits(__float22half2_rn(p3));
            hs16[(size_t)grow * 8 + c] = u;
        }
    }
#undef KSTEP
#undef ROWSTEP
}

// ================= scale: hs[n][:] *= dinv[n]  (after join) =================
__global__ void __launch_bounds__(256) k_scale() {
    int idx = blockIdx.x * blockDim.x + threadIdx.x;  // over NN*8 uint4
    if (idx >= NN * 8) return;
    int n = idx >> 3;
    float di = g_dinv[n];
    uint4* hs16 = reinterpret_cast<uint4*>(g_hs);
    uint4 u = hs16[idx];
    unsigned* up = &u.x;
#pragma unroll
    for (int p = 0; p < 4; p++) {
        __half2 h = *reinterpret_cast<__half2*>(&up[p]);
        float2 f = __half22float2(h);
        f.x *= di; f.y *= di;
        up[p] = h2_bits(__float22half2_rn(f));
    }
    hs16[idx] = u;
}

// ===== agg1: warp-per-node, 4 edges/iteration (8 lanes x 16B per row) =====
__global__ void __launch_bounds__(256) k_agg1(const float* __restrict__ b1) {
    int wg = (blockIdx.x * blockDim.x + threadIdx.x) >> 5;
    if (wg >= NN) return;
    const int d = wg;
    const int lane = threadIdx.x & 31;
    const int g  = lane >> 3;   // edge group 0..3
    const int fl = lane & 7;    // feature chunk: halves [fl*8, fl*8+8)

    const uint4* hs4 = reinterpret_cast<const uint4*>(g_hs);  // row = 8 uint4

    float facc[8];
#pragma unroll
    for (int p = 0; p < 8; p++) facc[p] = 0.0f;

    const int beg = g_off[d];
    const int cnt = g_indeg[d];
    for (int base = 0; base < cnt; base += 32) {
        int rem = cnt - base;
        int take = rem < 32 ? rem : 32;
        int s = 0;
        if (lane < take) s = g_csrc[beg + base + lane];
#pragma unroll
        for (int q = 0; q < 32; q += 4) {
            int eidx = q + g;
            int sj = __shfl_sync(0xffffffffu, s, eidx);
            if (eidx < take) {
                uint4 u = hs4[(size_t)sj * 8 + fl];
                const __half2* hp = reinterpret_cast<const __half2*>(&u);
#pragma unroll
                for (int p = 0; p < 4; p++) {
                    float2 f = __half22float2(hp[p]);
                    facc[2 * p]     += f.x;
                    facc[2 * p + 1] += f.y;
                }
            }
        }
    }

    // reduce across the 4 edge groups (lanes differing in bits 3,4)
#pragma unroll
    for (int off = 8; off < 32; off <<= 1) {
#pragma unroll
        for (int p = 0; p < 8; p++)
            facc[p] += __shfl_xor_sync(0xffffffffu, facc[p], off);
    }

    if (g == 0) {
        // add self row
        uint4 u = hs4[(size_t)d * 8 + fl];
        const __half2* hp = reinterpret_cast<const __half2*>(&u);
#pragma unroll
        for (int p = 0; p < 4; p++) {
            float2 f = __half22float2(hp[p]);
            facc[2 * p]     += f.x;
            facc[2 * p + 1] += f.y;
        }
        float di = g_dinv[d];
        const float4* b4 = reinterpret_cast<const float4*>(b1);
        float4 bb0 = b4[fl * 2];
        float4 bb1 = b4[fl * 2 + 1];
        float4 o0, o1;
        o0.x = fmaxf(fmaf(facc[0], di, bb0.x), 0.0f);
        o0.y = fmaxf(fmaf(facc[1], di, bb0.y), 0.0f);
        o0.z = fmaxf(fmaf(facc[2], di, bb0.z), 0.0f);
        o0.w = fmaxf(fmaf(facc[3], di, bb0.w), 0.0f);
        o1.x = fmaxf(fmaf(facc[4], di, bb1.x), 0.0f);
        o1.y = fmaxf(fmaf(facc[5], di, bb1.y), 0.0f);
        o1.z = fmaxf(fmaf(facc[6], di, bb1.z), 0.0f);
        o1.w = fmaxf(fmaf(facc[7], di, bb1.w), 0.0f);
        float4* aggp = reinterpret_cast<float4*>(g_agg + (size_t)d * FH + fl * 8);
        aggp[0] = o0;
        aggp[1] = o1;
    }
}

// ========== GEMM2: h2s = half((agg @ W2) * dinv[row]), fp16 stride-16 ==========
__global__ void __launch_bounds__(256) k_gemm2(const float* __restrict__ W2) {
    __shared__ float Ws[FH * FO];
    for (int i = threadIdx.x; i < FH * FO; i += blockDim.x) Ws[i] = W2[i];
    __syncthreads();

    int n = blockIdx.x * blockDim.x + threadIdx.x;
    if (n >= NN) return;

    float acc[FO];
#pragma unroll
    for (int j = 0; j < FO; j++) acc[j] = 0.0f;

    const float4* a4 = reinterpret_cast<const float4*>(g_agg + (size_t)n * FH);
#pragma unroll
    for (int k4 = 0; k4 < 16; k4++) {
        float4 a = a4[k4];
        float av[4] = {a.x, a.y, a.z, a.w};
#pragma unroll
        for (int kk = 0; kk < 4; kk++) {
            int k = k4 * 4 + kk;
#pragma unroll
            for (int j = 0; j < FO; j++) acc[j] = fmaf(av[kk], Ws[k * FO + j], acc[j]);
        }
    }

    float di = g_dinv[n];
    unsigned* o2 = reinterpret_cast<unsigned*>(g_h2s + (size_t)n * 16);
#pragma unroll
    for (int p = 0; p < 5; p++) {
        __half2 h = __float22half2_rn(make_float2(acc[p * 2] * di, acc[p * 2 + 1] * di));
        o2[p] = h2_bits(h);
    }
}

// ===== agg2: warp-per-node gather (shfl indices, fp16 rows, 5 active lanes) =====
__global__ void __launch_bounds__(256) k_agg2(const float* __restrict__ b2,
                                              float* __restrict__ out) {
    int wg = (blockIdx.x * blockDim.x + threadIdx.x) >> 5;
    if (wg >= NN) return;
    const int d = wg;
    const int lane = threadIdx.x & 31;

    const __half2* h2p = reinterpret_cast<const __half2*>(g_h2s);
    float2 acc = make_float2(0.f, 0.f);
    if (lane < 5) acc = __half22float2(h2p[(size_t)d * 8 + lane]);

    const int beg = g_off[d];
    const int cnt = g_indeg[d];
    for (int base = 0; base < cnt; base += 32) {
        int rem = cnt - base;
        int take = rem < 32 ? rem : 32;
        int s = 0;
        if (lane < take) s = g_csrc[beg + base + lane];
#pragma unroll 8
        for (int j = 0; j < take; j++) {
            int sj = __shfl_sync(0xffffffffu, s, j);
            if (lane < 5) {
                float2 v = __half22float2(h2p[(size_t)sj * 8 + lane]);
                acc.x += v.x;
                acc.y += v.y;
            }
        }
    }

    if (lane < 5) {
        float di = g_dinv[d];
        float* op = out + (size_t)d * FO;
        op[lane * 2]     = fmaf(acc.x, di, b2[lane * 2]);
        op[lane * 2 + 1] = fmaf(acc.y, di, b2[lane * 2 + 1]);
    }
}

extern "C" void kernel_launch(void* const* d_in, const int* in_sizes, int n_in,
                              void* d_out, int out_size) {
    const float* x  = (const float*)d_in[0];
    const int*   ei = (const int*)d_in[1];
    const float* W1 = (const float*)d_in[2];
    const float* b1 = (const float*)d_in[3];
    const float* W2 = (const float*)d_in[4];
    const float* b2 = (const float*)d_in[5];
    float* out = (float*)d_out;

    const int* src = ei;
    const int* dst = ei + NE;

    static bool init_done = false;
    static cudaStream_t s2;
    static cudaEvent_t ev_fork, ev_join;
    static void* indeg_ptr = nullptr;
    if (!init_done) {
        cudaFuncSetAttribute(k_gemm1, cudaFuncAttributeMaxDynamicSharedMemorySize,
                             GEMM1_SMEM);
        cudaStreamCreateWithFlags(&s2, cudaStreamNonBlocking);
        cudaEventCreateWithFlags(&ev_fork, cudaEventDisableTiming);
        cudaEventCreateWithFlags(&ev_join, cudaEventDisableTiming);
        cudaGetSymbolAddress(&indeg_ptr, g_indeg);
        init_done = true;
    }

    // ---- fork immediately: gemm1 has no input deps ----
    cudaEventRecord(ev_fork, 0);
    cudaStreamWaitEvent(s2, ev_fork, 0);
    k_gemm1<<<(NN + 255) / 256, 256, GEMM1_SMEM, s2>>>(x, W1);

    // ---- full prepass on capture stream, concurrent with gemm1 ----
    cudaMemsetAsync(indeg_ptr, 0, NN * sizeof(int), 0);
    k_indeg<<<(NE + 255) / 256, 256>>>(dst);
    k_scan1<<<NSCAN, SCAN_BLK>>>();
    k_scan_apply<<<(NN + 255) / 256, 256>>>();
    k_edge_pos<<<(NE + 255) / 256, 256>>>(src, dst);

    // ---- join ----
    cudaEventRecord(ev_join, s2);
    cudaStreamWaitEvent(0, ev_join, 0);

    k_scale<<<(NN * 8 + 255) / 256, 256>>>();
    k_agg1<<<(NN * 32 + 255) / 256, 256>>>(b1);
    k_gemm2<<<(NN + 255) / 256, 256>>>(W2);
    k_agg2<<<(NN * 32 + 255) / 256, 256>>>(b2, out);
}

// round 11
// speedup vs baseline: 1.4852x; 1.1450x over previous
#include <cuda_runtime.h>
#include <cuda_fp16.h>

#define NN 100000
#define NE 1600000
#define FIN 128
#define FH  64
#define FO  10

#define SCAN_BLK 512
#define NSCAN ((NN + SCAN_BLK - 1) / SCAN_BLK)   // 196

typedef unsigned long long u64;

// ---- scratch (device globals; no allocation allowed) ----
__device__ int   g_indeg[NN];
__device__ int   g_off[NN];
__device__ int   g_cursor[NN];
__device__ int   g_offp[NN];
__device__ int   g_bsum[NSCAN];
__device__ int   g_csrc[NE];
__device__ float g_dinv[NN];
__device__ __align__(16) __half g_hs[NN * FH];    // x@W1 (unscaled, then *= dinv)
__device__ __align__(16) __half g_aggh[NN * FH];  // fp16 relu(b1+dinv*(...)), 128B rows
__device__ __align__(16) __half g_h2s[NN * 16];   // (agg@W2)*dinv, fp16, stride 16

// ---- packed f32x2 helpers ----
__device__ __forceinline__ u64 dup2(float v) {
    u64 d; asm("mov.b64 %0, {%1,%1};" : "=l"(d) : "f"(v)); return d;
}
__device__ __forceinline__ void ffma2(u64& d, u64 a, u64 b) {
    asm("fma.rn.f32x2 %0, %1, %2, %0;" : "+l"(d) : "l"(a), "l"(b));
}
__device__ __forceinline__ float2 unpack2(u64 d) {
    float lo, hi; asm("mov.b64 {%0,%1}, %2;" : "=f"(lo), "=f"(hi) : "l"(d));
    return make_float2(lo, hi);
}
__device__ __forceinline__ unsigned h2_bits(__half2 h) {
    return *reinterpret_cast<unsigned*>(&h);
}

// ================= degree =================
__global__ void k_indeg(const int* __restrict__ dst) {
    int e = blockIdx.x * blockDim.x + threadIdx.x;
    if (e < NE) atomicAdd(&g_indeg[dst[e]], 1);
}

// ================= scan pass 1 (+ dinv fused) =================
__global__ void __launch_bounds__(SCAN_BLK) k_scan1() {
    int i = blockIdx.x * SCAN_BLK + threadIdx.x;
    int v = (i < NN) ? g_indeg[i] : 0;
    if (i < NN) g_dinv[i] = rsqrtf(1.0f + (float)v);
    int lane = threadIdx.x & 31, w = threadIdx.x >> 5;
    int s = v;
#pragma unroll
    for (int o = 1; o < 32; o <<= 1) {
        int t = __shfl_up_sync(0xffffffffu, s, o);
        if (lane >= o) s += t;
    }
    __shared__ int wsum[16];
    if (lane == 31) wsum[w] = s;
    __syncthreads();
    if (w == 0) {
        int t = (lane < 16) ? wsum[lane] : 0;
#pragma unroll
        for (int o = 1; o < 16; o <<= 1) {
            int u = __shfl_up_sync(0xffffffffu, t, o);
            if (lane >= o) t += u;
        }
        if (lane < 16) wsum[lane] = t;
    }
    __syncthreads();
    int excl = s - v + ((w > 0) ? wsum[w - 1] : 0);
    if (i < NN) g_offp[i] = excl;
    if (threadIdx.x == 0) g_bsum[blockIdx.x] = wsum[15];
}

// ===== scan pass 2 fused into apply: every block scans the 196 block sums =====
__global__ void __launch_bounds__(256) k_scan_apply() {
    __shared__ int s_ex[256];
    int tid = threadIdx.x;
    {
        int v = (tid < NSCAN) ? g_bsum[tid] : 0;
        int lane = tid & 31, w = tid >> 5;
        int s = v;
#pragma unroll
        for (int o = 1; o < 32; o <<= 1) {
            int t = __shfl_up_sync(0xffffffffu, s, o);
            if (lane >= o) s += t;
        }
        __shared__ int wsum[8];
        if (lane == 31) wsum[w] = s;
        __syncthreads();
        if (w == 0) {
            int t = (lane < 8) ? wsum[lane] : 0;
#pragma unroll
            for (int o = 1; o < 8; o <<= 1) {
                int u = __shfl_up_sync(0xffffffffu, t, o);
                if (lane >= o) t += u;
            }
            if (lane < 8) wsum[lane] = t;
        }
        __syncthreads();
        s_ex[tid] = s - v + ((w > 0) ? wsum[w - 1] : 0);  // exclusive
        __syncthreads();
    }
    int i = blockIdx.x * 256 + tid;
    if (i < NN) {
        int o = g_offp[i] + s_ex[i >> 9];
        g_off[i] = o;
        g_cursor[i] = o;
    }
}

// ================= CSR positional scatter =================
__global__ void k_edge_pos(const int* __restrict__ src, const int* __restrict__ dst) {
    int e = blockIdx.x * blockDim.x + threadIdx.x;
    if (e < NE) {
        int pos = atomicAdd(&g_cursor[dst[e]], 1);
        g_csrc[pos] = src[e];
    }
}

// ================= GEMM1: hs = half(x @ W1)  (unscaled; no deps) =============
#define XS_F4 (256 * 17)
#define GEMM1_SMEM (XS_F4 * 16 + 64 * 64 * 4)   // 86016 B

__global__ void __launch_bounds__(256, 2) k_gemm1(const float* __restrict__ x,
                                                  const float* __restrict__ W1) {
    extern __shared__ float4 sm4[];
    float4* xs4 = sm4;                     // [256][17]
    float*  Ws  = (float*)(sm4 + XS_F4);   // [64][64]

    const int tid = threadIdx.x;
    const int c  = tid & 7;
    const int rg = tid >> 3;
    const int row_base = blockIdx.x * 256;

    u64 acc[8][4];
#pragma unroll
    for (int i = 0; i < 8; i++)
#pragma unroll
        for (int p = 0; p < 4; p++) acc[i][p] = 0ull;

    const float4* x4  = reinterpret_cast<const float4*>(x);
    const float4* W14 = reinterpret_cast<const float4*>(W1);
    float4* Ws4 = reinterpret_cast<float4*>(Ws);

    for (int kc = 0; kc < 2; kc++) {
#pragma unroll
        for (int j = 0; j < 16; j++) {
            int f = tid + 256 * j;
            int row = f >> 4;
            int kq  = f & 15;
            int grow = min(row_base + row, NN - 1);
            xs4[row * 17 + kq] = x4[(size_t)grow * 32 + kc * 16 + kq];
        }
#pragma unroll
        for (int j = 0; j < 4; j++) {
            int f = tid + 256 * j;
            Ws4[f] = W14[kc * 1024 + f];
        }
        __syncthreads();

#define ROWSTEP(i, comp)                                   \
        {                                                  \
            u64 xd = dup2(xq[i].comp);                     \
            ffma2(acc[i][0], xd, wA.x);                    \
            ffma2(acc[i][1], xd, wA.y);                    \
            ffma2(acc[i][2], xd, wB.x);                    \
            ffma2(acc[i][3], xd, wB.y);                    \
        }
#define KSTEP(comp, kk)                                                        \
        {                                                                      \
            const ulonglong2* wr =                                             \
                (const ulonglong2*)(Ws + (k4 * 4 + kk) * 64 + c * 8);          \
            ulonglong2 wA = wr[0];                                             \
            ulonglong2 wB = wr[1];                                             \
            ROWSTEP(0, comp) ROWSTEP(1, comp) ROWSTEP(2, comp) ROWSTEP(3, comp)\
            ROWSTEP(4, comp) ROWSTEP(5, comp) ROWSTEP(6, comp) ROWSTEP(7, comp)\
        }

#pragma unroll 4
        for (int k4 = 0; k4 < 16; k4++) {
            float4 xq[8];
#pragma unroll
            for (int i = 0; i < 8; i++) xq[i] = xs4[(rg + 32 * i) * 17 + k4];
            KSTEP(x, 0)
            KSTEP(y, 1)
            KSTEP(z, 2)
            KSTEP(w, 3)
        }
        __syncthreads();
    }

    uint4* hs16 = reinterpret_cast<uint4*>(g_hs);
#pragma unroll
    for (int i = 0; i < 8; i++) {
        int grow = row_base + rg + 32 * i;
        if (grow < NN) {
            float2 p0 = unpack2(acc[i][0]);
            float2 p1 = unpack2(acc[i][1]);
            float2 p2 = unpack2(acc[i][2]);
            float2 p3 = unpack2(acc[i][3]);
            uint4 u;
            u.x = h2_bits(__float22half2_rn(p0));
            u.y = h2_bits(__float22half2_rn(p1));
            u.z = h2_bits(__float22half2_rn(p2));
            u.w = h2_bits(__float22half2_rn(p3));
            hs16[(size_t)grow * 8 + c] = u;
        }
    }
#undef KSTEP
#undef ROWSTEP
}

// ================= scale: hs[n][:] *= dinv[n]  (on s2, overlapped) ===========
__global__ void __launch_bounds__(256) k_scale() {
    int idx = blockIdx.x * blockDim.x + threadIdx.x;  // over NN*8 uint4
    if (idx >= NN * 8) return;
    int n = idx >> 3;
    float di = g_dinv[n];
    uint4* hs16 = reinterpret_cast<uint4*>(g_hs);
    uint4 u = hs16[idx];
    unsigned* up = &u.x;
#pragma unroll
    for (int p = 0; p < 4; p++) {
        __half2 h = *reinterpret_cast<__half2*>(&up[p]);
        float2 f = __half22float2(h);
        f.x *= di; f.y *= di;
        up[p] = h2_bits(__float22half2_rn(f));
    }
    hs16[idx] = u;
}

// ===== agg1: warp-per-node, 4 edges/iteration; fp16 agg output =====
__global__ void __launch_bounds__(256) k_agg1(const float* __restrict__ b1) {
    int wg = (blockIdx.x * blockDim.x + threadIdx.x) >> 5;
    if (wg >= NN) return;
    const int d = wg;
    const int lane = threadIdx.x & 31;
    const int g  = lane >> 3;   // edge group 0..3
    const int fl = lane & 7;    // feature chunk: halves [fl*8, fl*8+8)

    const uint4* hs4 = reinterpret_cast<const uint4*>(g_hs);  // row = 8 uint4

    float facc[8];
#pragma unroll
    for (int p = 0; p < 8; p++) facc[p] = 0.0f;

    const int beg = g_off[d];
    const int cnt = g_indeg[d];
    for (int base = 0; base < cnt; base += 32) {
        int rem = cnt - base;
        int take = rem < 32 ? rem : 32;
        int s = 0;
        if (lane < take) s = g_csrc[beg + base + lane];
#pragma unroll
        for (int q = 0; q < 32; q += 4) {
            int eidx = q + g;
            int sj = __shfl_sync(0xffffffffu, s, eidx);
            if (eidx < take) {
                uint4 u = hs4[(size_t)sj * 8 + fl];
                const __half2* hp = reinterpret_cast<const __half2*>(&u);
#pragma unroll
                for (int p = 0; p < 4; p++) {
                    float2 f = __half22float2(hp[p]);
                    facc[2 * p]     += f.x;
                    facc[2 * p + 1] += f.y;
                }
            }
        }
    }

    // reduce across the 4 edge groups
#pragma unroll
    for (int off = 8; off < 32; off <<= 1) {
#pragma unroll
        for (int p = 0; p < 8; p++)
            facc[p] += __shfl_xor_sync(0xffffffffu, facc[p], off);
    }

    if (g == 0) {
        uint4 u = hs4[(size_t)d * 8 + fl];
        const __half2* hp = reinterpret_cast<const __half2*>(&u);
#pragma unroll
        for (int p = 0; p < 4; p++) {
            float2 f = __half22float2(hp[p]);
            facc[2 * p]     += f.x;
            facc[2 * p + 1] += f.y;
        }
        float di = g_dinv[d];
        const float4* b4 = reinterpret_cast<const float4*>(b1);
        float4 bb0 = b4[fl * 2];
        float4 bb1 = b4[fl * 2 + 1];
        float o0 = fmaxf(fmaf(facc[0], di, bb0.x), 0.0f);
        float o1 = fmaxf(fmaf(facc[1], di, bb0.y), 0.0f);
        float o2 = fmaxf(fmaf(facc[2], di, bb0.z), 0.0f);
        float o3 = fmaxf(fmaf(facc[3], di, bb0.w), 0.0f);
        float o4 = fmaxf(fmaf(facc[4], di, bb1.x), 0.0f);
        float o5 = fmaxf(fmaf(facc[5], di, bb1.y), 0.0f);
        float o6 = fmaxf(fmaf(facc[6], di, bb1.z), 0.0f);
        float o7 = fmaxf(fmaf(facc[7], di, bb1.w), 0.0f);
        uint4 w;
        w.x = h2_bits(__float22half2_rn(make_float2(o0, o1)));
        w.y = h2_bits(__float22half2_rn(make_float2(o2, o3)));
        w.z = h2_bits(__float22half2_rn(make_float2(o4, o5)));
        w.w = h2_bits(__float22half2_rn(make_float2(o6, o7)));
        reinterpret_cast<uint4*>(g_aggh)[(size_t)d * 8 + fl] = w;
    }
}

// ========== GEMM2: h2s = half((aggh @ W2) * dinv[row]), fp16 inputs ==========
__global__ void __launch_bounds__(256) k_gemm2(const float* __restrict__ W2) {
    __shared__ float Ws[FH * FO];
    for (int i = threadIdx.x; i < FH * FO; i += blockDim.x) Ws[i] = W2[i];
    __syncthreads();

    int n = blockIdx.x * blockDim.x + threadIdx.x;
    if (n >= NN) return;

    float acc[FO];
#pragma unroll
    for (int j = 0; j < FO; j++) acc[j] = 0.0f;

    const uint4* a4 = reinterpret_cast<const uint4*>(g_aggh) + (size_t)n * 8;
#pragma unroll
    for (int k4 = 0; k4 < 8; k4++) {
        uint4 u = a4[k4];
        const __half2* hp = reinterpret_cast<const __half2*>(&u);
#pragma unroll
        for (int pp = 0; pp < 4; pp++) {
            float2 f = __half22float2(hp[pp]);
            int k = k4 * 8 + pp * 2;
#pragma unroll
            for (int j = 0; j < FO; j++) acc[j] = fmaf(f.x, Ws[k * FO + j], acc[j]);
#pragma unroll
            for (int j = 0; j < FO; j++) acc[j] = fmaf(f.y, Ws[(k + 1) * FO + j], acc[j]);
        }
    }

    float di = g_dinv[n];
    unsigned* o2 = reinterpret_cast<unsigned*>(g_h2s + (size_t)n * 16);
#pragma unroll
    for (int p = 0; p < 5; p++) {
        __half2 h = __float22half2_rn(make_float2(acc[p * 2] * di, acc[p * 2 + 1] * di));
        o2[p] = h2_bits(h);
    }
}

// ===== agg2: warp-per-node, 4 edges/iteration (8 lanes/edge, fl<5 active) =====
__global__ void __launch_bounds__(256) k_agg2(const float* __restrict__ b2,
                                              float* __restrict__ out) {
    int wg = (blockIdx.x * blockDim.x + threadIdx.x) >> 5;
    if (wg >= NN) return;
    const int d = wg;
    const int lane = threadIdx.x & 31;
    const int g  = lane >> 3;
    const int fl = lane & 7;

    const __half2* h2p = reinterpret_cast<const __half2*>(g_h2s);  // row = 8 half2

    float2 acc = make_float2(0.f, 0.f);

    const int beg = g_off[d];
    const int cnt = g_indeg[d];
    for (int base = 0; base < cnt; base += 32) {
        int rem = cnt - base;
        int take = rem < 32 ? rem : 32;
        int s = 0;
        if (lane < take) s = g_csrc[beg + base + lane];
#pragma unroll
        for (int q = 0; q < 32; q += 4) {
            int eidx = q + g;
            int sj = __shfl_sync(0xffffffffu, s, eidx);
            if (eidx < take && fl < 5) {
                float2 v = __half22float2(h2p[(size_t)sj * 8 + fl]);
                acc.x += v.x;
                acc.y += v.y;
            }
        }
    }

    // reduce across the 4 edge groups
#pragma unroll
    for (int off = 8; off < 32; off <<= 1) {
        acc.x += __shfl_xor_sync(0xffffffffu, acc.x, off);
        acc.y += __shfl_xor_sync(0xffffffffu, acc.y, off);
    }

    if (g == 0 && fl < 5) {
        float2 self = __half22float2(h2p[(size_t)d * 8 + fl]);
        acc.x += self.x;
        acc.y += self.y;
        float di = g_dinv[d];
        float* op = out + (size_t)d * FO;
        op[fl * 2]     = fmaf(acc.x, di, b2[fl * 2]);
        op[fl * 2 + 1] = fmaf(acc.y, di, b2[fl * 2 + 1]);
    }
}

extern "C" void kernel_launch(void* const* d_in, const int* in_sizes, int n_in,
                              void* d_out, int out_size) {
    const float* x  = (const float*)d_in[0];
    const int*   ei = (const int*)d_in[1];
    const float* W1 = (const float*)d_in[2];
    const float* b1 = (const float*)d_in[3];
    const float* W2 = (const float*)d_in[4];
    const float* b2 = (const float*)d_in[5];
    float* out = (float*)d_out;

    const int* src = ei;
    const int* dst = ei + NE;

    static bool init_done = false;
    static cudaStream_t s2;
    static cudaEvent_t ev_fork, ev_scan1, ev_join;
    static void* indeg_ptr = nullptr;
    if (!init_done) {
        cudaFuncSetAttribute(k_gemm1, cudaFuncAttributeMaxDynamicSharedMemorySize,
                             GEMM1_SMEM);
        cudaStreamCreateWithFlags(&s2, cudaStreamNonBlocking);
        cudaEventCreateWithFlags(&ev_fork, cudaEventDisableTiming);
        cudaEventCreateWithFlags(&ev_scan1, cudaEventDisableTiming);
        cudaEventCreateWithFlags(&ev_join, cudaEventDisableTiming);
        cudaGetSymbolAddress(&indeg_ptr, g_indeg);
        init_done = true;
    }

    // ---- fork immediately: gemm1 has no input deps ----
    cudaEventRecord(ev_fork, 0);
    cudaStreamWaitEvent(s2, ev_fork, 0);
    k_gemm1<<<(NN + 255) / 256, 256, GEMM1_SMEM, s2>>>(x, W1);

    // ---- prepass on capture stream, concurrent with gemm1 ----
    cudaMemsetAsync(indeg_ptr, 0, NN * sizeof(int), 0);
    k_indeg<<<(NE + 255) / 256, 256>>>(dst);
    k_scan1<<<NSCAN, SCAN_BLK>>>();
    cudaEventRecord(ev_scan1, 0);

    // s2: scale hs as soon as gemm1 + scan1 are both done (overlaps edge_pos)
    cudaStreamWaitEvent(s2, ev_scan1, 0);
    k_scale<<<(NN * 8 + 255) / 256, 256, 0, s2>>>();

    k_scan_apply<<<(NN + 255) / 256, 256>>>();
    k_edge_pos<<<(NE + 255) / 256, 256>>>(src, dst);

    // ---- join ----
    cudaEventRecord(ev_join, s2);
    cudaStreamWaitEvent(0, ev_join, 0);

    k_agg1<<<(NN * 32 + 255) / 256, 256>>>(b1);
    k_gemm2<<<(NN + 255) / 256, 256>>>(W2);
    k_agg2<<<(NN * 32 + 255) / 256, 256>>>(b2, out);
}

// round 12
// speedup vs baseline: 1.5659x; 1.0543x over previous
#include <cuda_runtime.h>
#include <cuda_fp16.h>

#define NN 100000
#define NE 1600000
#define FIN 128
#define FH  64
#define FO  10

#define SCAN_BLK 512
#define NSCAN ((NN + SCAN_BLK - 1) / SCAN_BLK)   // 196

typedef unsigned long long u64;

// ---- scratch (device globals; no allocation allowed) ----
__device__ int   g_indeg[NN];
__device__ int   g_off[NN];
__device__ int   g_cursor[NN];
__device__ int   g_offp[NN];
__device__ int   g_bsum[NSCAN];
__device__ int   g_csrc[NE];
__device__ float g_dinv[NN];
__device__ __align__(16) __half g_hs[NN * FH];    // x@W1 (unscaled, then *= dinv)
__device__ __align__(16) __half g_aggh[NN * FH];  // fp16 relu(b1+dinv*(...)), 128B rows
__device__ __align__(16) __half g_h2s[NN * 16];   // (agg@W2)*dinv, fp16, stride 16

// ---- packed f32x2 helpers ----
__device__ __forceinline__ u64 dup2(float v) {
    u64 d; asm("mov.b64 %0, {%1,%1};" : "=l"(d) : "f"(v)); return d;
}
__device__ __forceinline__ void ffma2(u64& d, u64 a, u64 b) {
    asm("fma.rn.f32x2 %0, %1, %2, %0;" : "+l"(d) : "l"(a), "l"(b));
}
__device__ __forceinline__ float2 unpack2(u64 d) {
    float lo, hi; asm("mov.b64 {%0,%1}, %2;" : "=f"(lo), "=f"(hi) : "l"(d));
    return make_float2(lo, hi);
}
__device__ __forceinline__ unsigned h2_bits(__half2 h) {
    return *reinterpret_cast<unsigned*>(&h);
}

// ================= degree =================
__global__ void k_indeg(const int* __restrict__ dst) {
    int e = blockIdx.x * blockDim.x + threadIdx.x;
    if (e < NE) atomicAdd(&g_indeg[dst[e]], 1);
}

// ================= scan pass 1 (+ dinv fused) =================
__global__ void __launch_bounds__(SCAN_BLK) k_scan1() {
    int i = blockIdx.x * SCAN_BLK + threadIdx.x;
    int v = (i < NN) ? g_indeg[i] : 0;
    if (i < NN) g_dinv[i] = rsqrtf(1.0f + (float)v);
    int lane = threadIdx.x & 31, w = threadIdx.x >> 5;
    int s = v;
#pragma unroll
    for (int o = 1; o < 32; o <<= 1) {
        int t = __shfl_up_sync(0xffffffffu, s, o);
        if (lane >= o) s += t;
    }
    __shared__ int wsum[16];
    if (lane == 31) wsum[w] = s;
    __syncthreads();
    if (w == 0) {
        int t = (lane < 16) ? wsum[lane] : 0;
#pragma unroll
        for (int o = 1; o < 16; o <<= 1) {
            int u = __shfl_up_sync(0xffffffffu, t, o);
            if (lane >= o) t += u;
        }
        if (lane < 16) wsum[lane] = t;
    }
    __syncthreads();
    int excl = s - v + ((w > 0) ? wsum[w - 1] : 0);
    if (i < NN) g_offp[i] = excl;
    if (threadIdx.x == 0) g_bsum[blockIdx.x] = wsum[15];
}

// ===== scan pass 2 fused into apply: every block scans the 196 block sums =====
__global__ void __launch_bounds__(256) k_scan_apply() {
    __shared__ int s_ex[256];
    int tid = threadIdx.x;
    {
        int v = (tid < NSCAN) ? g_bsum[tid] : 0;
        int lane = tid & 31, w = tid >> 5;
        int s = v;
#pragma unroll
        for (int o = 1; o < 32; o <<= 1) {
            int t = __shfl_up_sync(0xffffffffu, s, o);
            if (lane >= o) s += t;
        }
        __shared__ int wsum[8];
        if (lane == 31) wsum[w] = s;
        __syncthreads();
        if (w == 0) {
            int t = (lane < 8) ? wsum[lane] : 0;
#pragma unroll
            for (int o = 1; o < 8; o <<= 1) {
                int u = __shfl_up_sync(0xffffffffu, t, o);
                if (lane >= o) t += u;
            }
            if (lane < 8) wsum[lane] = t;
        }
        __syncthreads();
        s_ex[tid] = s - v + ((w > 0) ? wsum[w - 1] : 0);  // exclusive
        __syncthreads();
    }
    int i = blockIdx.x * 256 + tid;
    if (i < NN) {
        int o = g_offp[i] + s_ex[i >> 9];
        g_off[i] = o;
        g_cursor[i] = o;
    }
}

// ================= CSR positional scatter =================
__global__ void k_edge_pos(const int* __restrict__ src, const int* __restrict__ dst) {
    int e = blockIdx.x * blockDim.x + threadIdx.x;
    if (e < NE) {
        int pos = atomicAdd(&g_cursor[dst[e]], 1);
        g_csrc[pos] = src[e];
    }
}

// ================= GEMM1: hs = half(x @ W1)  (unscaled; no deps) =============
#define XS_F4 (256 * 17)
#define GEMM1_SMEM (XS_F4 * 16 + 64 * 64 * 4)   // 86016 B

__global__ void __launch_bounds__(256, 2) k_gemm1(const float* __restrict__ x,
                                                  const float* __restrict__ W1) {
    extern __shared__ float4 sm4[];
    float4* xs4 = sm4;                     // [256][17]
    float*  Ws  = (float*)(sm4 + XS_F4);   // [64][64]

    const int tid = threadIdx.x;
    const int c  = tid & 7;
    const int rg = tid >> 3;
    const int row_base = blockIdx.x * 256;

    u64 acc[8][4];
#pragma unroll
    for (int i = 0; i < 8; i++)
#pragma unroll
        for (int p = 0; p < 4; p++) acc[i][p] = 0ull;

    const float4* x4  = reinterpret_cast<const float4*>(x);
    const float4* W14 = reinterpret_cast<const float4*>(W1);
    float4* Ws4 = reinterpret_cast<float4*>(Ws);

    for (int kc = 0; kc < 2; kc++) {
#pragma unroll
        for (int j = 0; j < 16; j++) {
            int f = tid + 256 * j;
            int row = f >> 4;
            int kq  = f & 15;
            int grow = min(row_base + row, NN - 1);
            xs4[row * 17 + kq] = x4[(size_t)grow * 32 + kc * 16 + kq];
        }
#pragma unroll
        for (int j = 0; j < 4; j++) {
            int f = tid + 256 * j;
            Ws4[f] = W14[kc * 1024 + f];
        }
        __syncthreads();

#define ROWSTEP(i, comp)                                   \
        {                                                  \
            u64 xd = dup2(xq[i].comp);                     \
            ffma2(acc[i][0], xd, wA.x);                    \
            ffma2(acc[i][1], xd, wA.y);                    \
            ffma2(acc[i][2], xd, wB.x);                    \
            ffma2(acc[i][3], xd, wB.y);                    \
        }
#define KSTEP(comp, kk)                                                        \
        {                                                                      \
            const ulonglong2* wr =                                             \
                (const ulonglong2*)(Ws + (k4 * 4 + kk) * 64 + c * 8);          \
            ulonglong2 wA = wr[0];                                             \
            ulonglong2 wB = wr[1];                                             \
            ROWSTEP(0, comp) ROWSTEP(1, comp) ROWSTEP(2, comp) ROWSTEP(3, comp)\
            ROWSTEP(4, comp) ROWSTEP(5, comp) ROWSTEP(6, comp) ROWSTEP(7, comp)\
        }

#pragma unroll 4
        for (int k4 = 0; k4 < 16; k4++) {
            float4 xq[8];
#pragma unroll
            for (int i = 0; i < 8; i++) xq[i] = xs4[(rg + 32 * i) * 17 + k4];
            KSTEP(x, 0)
            KSTEP(y, 1)
            KSTEP(z, 2)
            KSTEP(w, 3)
        }
        __syncthreads();
    }

    uint4* hs16 = reinterpret_cast<uint4*>(g_hs);
#pragma unroll
    for (int i = 0; i < 8; i++) {
        int grow = row_base + rg + 32 * i;
        if (grow < NN) {
            float2 p0 = unpack2(acc[i][0]);
            float2 p1 = unpack2(acc[i][1]);
            float2 p2 = unpack2(acc[i][2]);
            float2 p3 = unpack2(acc[i][3]);
            uint4 u;
            u.x = h2_bits(__float22half2_rn(p0));
            u.y = h2_bits(__float22half2_rn(p1));
            u.z = h2_bits(__float22half2_rn(p2));
            u.w = h2_bits(__float22half2_rn(p3));
            hs16[(size_t)grow * 8 + c] = u;
        }
    }
#undef KSTEP
#undef ROWSTEP
}

// ================= scale: hs[n][:] *= dinv[n]  (on s2, overlapped) ===========
__global__ void __launch_bounds__(256) k_scale() {
    int idx = blockIdx.x * blockDim.x + threadIdx.x;  // over NN*8 uint4
    if (idx >= NN * 8) return;
    int n = idx >> 3;
    float di = g_dinv[n];
    uint4* hs16 = reinterpret_cast<uint4*>(g_hs);
    uint4 u = hs16[idx];
    unsigned* up = &u.x;
#pragma unroll
    for (int p = 0; p < 4; p++) {
        __half2 h = *reinterpret_cast<__half2*>(&up[p]);
        float2 f = __half22float2(h);
        f.x *= di; f.y *= di;
        up[p] = h2_bits(__float22half2_rn(f));
    }
    hs16[idx] = u;
}

// ===== agg1: warp-per-node, 2x4 edges/iteration, pairwise HADD2 combine =====
__global__ void __launch_bounds__(256) k_agg1(const float* __restrict__ b1) {
    int wg = (blockIdx.x * blockDim.x + threadIdx.x) >> 5;
    if (wg >= NN) return;
    const int d = wg;
    const int lane = threadIdx.x & 31;
    const int g  = lane >> 3;   // edge group 0..3
    const int fl = lane & 7;    // feature chunk: halves [fl*8, fl*8+8)

    const uint4* hs4 = reinterpret_cast<const uint4*>(g_hs);  // row = 8 uint4

    float facc[8];
#pragma unroll
    for (int p = 0; p < 8; p++) facc[p] = 0.0f;

    const int beg = g_off[d];
    const int cnt = g_indeg[d];
    for (int base = 0; base < cnt; base += 32) {
        int rem = cnt - base;
        int take = rem < 32 ? rem : 32;
        int s = 0;
        if (lane < take) s = g_csrc[beg + base + lane];
#pragma unroll
        for (int q = 0; q < 32; q += 8) {
            int e0 = q + g;
            int e1 = q + 4 + g;
            int s0 = __shfl_sync(0xffffffffu, s, e0);
            int s1 = __shfl_sync(0xffffffffu, s, e1);
            if (e0 < take) {
                uint4 u0 = hs4[(size_t)s0 * 8 + fl];
                uint4 u1 = make_uint4(0u, 0u, 0u, 0u);
                if (e1 < take) u1 = hs4[(size_t)s1 * 8 + fl];
                const __half2* h0 = reinterpret_cast<const __half2*>(&u0);
                const __half2* h1 = reinterpret_cast<const __half2*>(&u1);
#pragma unroll
                for (int p = 0; p < 4; p++) {
                    __half2 hsum = __hadd2(h0[p], h1[p]);
                    float2 f = __half22float2(hsum);
                    facc[2 * p]     += f.x;
                    facc[2 * p + 1] += f.y;
                }
            }
        }
    }

    // reduce across the 4 edge groups
#pragma unroll
    for (int off = 8; off < 32; off <<= 1) {
#pragma unroll
        for (int p = 0; p < 8; p++)
            facc[p] += __shfl_xor_sync(0xffffffffu, facc[p], off);
    }

    if (g == 0) {
        uint4 u = hs4[(size_t)d * 8 + fl];
        const __half2* hp = reinterpret_cast<const __half2*>(&u);
#pragma unroll
        for (int p = 0; p < 4; p++) {
            float2 f = __half22float2(hp[p]);
            facc[2 * p]     += f.x;
            facc[2 * p + 1] += f.y;
        }
        float di = g_dinv[d];
        const float4* b4 = reinterpret_cast<const float4*>(b1);
        float4 bb0 = b4[fl * 2];
        float4 bb1 = b4[fl * 2 + 1];
        float o0 = fmaxf(fmaf(facc[0], di, bb0.x), 0.0f);
        float o1 = fmaxf(fmaf(facc[1], di, bb0.y), 0.0f);
        float o2 = fmaxf(fmaf(facc[2], di, bb0.z), 0.0f);
        float o3 = fmaxf(fmaf(facc[3], di, bb0.w), 0.0f);
        float o4 = fmaxf(fmaf(facc[4], di, bb1.x), 0.0f);
        float o5 = fmaxf(fmaf(facc[5], di, bb1.y), 0.0f);
        float o6 = fmaxf(fmaf(facc[6], di, bb1.z), 0.0f);
        float o7 = fmaxf(fmaf(facc[7], di, bb1.w), 0.0f);
        uint4 w;
        w.x = h2_bits(__float22half2_rn(make_float2(o0, o1)));
        w.y = h2_bits(__float22half2_rn(make_float2(o2, o3)));
        w.z = h2_bits(__float22half2_rn(make_float2(o4, o5)));
        w.w = h2_bits(__float22half2_rn(make_float2(o6, o7)));
        reinterpret_cast<uint4*>(g_aggh)[(size_t)d * 8 + fl] = w;
    }
}

// ========== GEMM2: h2s = half((aggh @ W2) * dinv[row]), fp16 inputs ==========
__global__ void __launch_bounds__(256) k_gemm2(const float* __restrict__ W2) {
    __shared__ float Ws[FH * FO];
    for (int i = threadIdx.x; i < FH * FO; i += blockDim.x) Ws[i] = W2[i];
    __syncthreads();

    int n = blockIdx.x * blockDim.x + threadIdx.x;
    if (n >= NN) return;

    float acc[FO];
#pragma unroll
    for (int j = 0; j < FO; j++) acc[j] = 0.0f;

    const uint4* a4 = reinterpret_cast<const uint4*>(g_aggh) + (size_t)n * 8;
#pragma unroll
    for (int k4 = 0; k4 < 8; k4++) {
        uint4 u = a4[k4];
        const __half2* hp = reinterpret_cast<const __half2*>(&u);
#pragma unroll
        for (int pp = 0; pp < 4; pp++) {
            float2 f = __half22float2(hp[pp]);
            int k = k4 * 8 + pp * 2;
#pragma unroll
            for (int j = 0; j < FO; j++) acc[j] = fmaf(f.x, Ws[k * FO + j], acc[j]);
#pragma unroll
            for (int j = 0; j < FO; j++) acc[j] = fmaf(f.y, Ws[(k + 1) * FO + j], acc[j]);
        }
    }

    float di = g_dinv[n];
    unsigned* o2 = reinterpret_cast<unsigned*>(g_h2s + (size_t)n * 16);
#pragma unroll
    for (int p = 0; p < 5; p++) {
        __half2 h = __float22half2_rn(make_float2(acc[p * 2] * di, acc[p * 2 + 1] * di));
        o2[p] = h2_bits(h);
    }
}

// ===== agg2: warp-per-node, 2x4 edges/iteration, pairwise HADD2 combine =====
__global__ void __launch_bounds__(256) k_agg2(const float* __restrict__ b2,
                                              float* __restrict__ out) {
    int wg = (blockIdx.x * blockDim.x + threadIdx.x) >> 5;
    if (wg >= NN) return;
    const int d = wg;
    const int lane = threadIdx.x & 31;
    const int g  = lane >> 3;
    const int fl = lane & 7;

    const __half2* h2p = reinterpret_cast<const __half2*>(g_h2s);  // row = 8 half2

    float2 acc = make_float2(0.f, 0.f);

    const int beg = g_off[d];
    const int cnt = g_indeg[d];
    for (int base = 0; base < cnt; base += 32) {
        int rem = cnt - base;
        int take = rem < 32 ? rem : 32;
        int s = 0;
        if (lane < take) s = g_csrc[beg + base + lane];
#pragma unroll
        for (int q = 0; q < 32; q += 8) {
            int e0 = q + g;
            int e1 = q + 4 + g;
            int s0 = __shfl_sync(0xffffffffu, s, e0);
            int s1 = __shfl_sync(0xffffffffu, s, e1);
            if (e0 < take && fl < 5) {
                __half2 v0 = h2p[(size_t)s0 * 8 + fl];
                __half2 v1 = __float2half2_rn(0.0f);
                if (e1 < take) v1 = h2p[(size_t)s1 * 8 + fl];
                float2 f = __half22float2(__hadd2(v0, v1));
                acc.x += f.x;
                acc.y += f.y;
            }
        }
    }

    // reduce across the 4 edge groups
#pragma unroll
    for (int off = 8; off < 32; off <<= 1) {
        acc.x += __shfl_xor_sync(0xffffffffu, acc.x, off);
        acc.y += __shfl_xor_sync(0xffffffffu, acc.y, off);
    }

    if (g == 0 && fl < 5) {
        float2 self = __half22float2(h2p[(size_t)d * 8 + fl]);
        acc.x += self.x;
        acc.y += self.y;
        float di = g_dinv[d];
        float* op = out + (size_t)d * FO;
        op[fl * 2]     = fmaf(acc.x, di, b2[fl * 2]);
        op[fl * 2 + 1] = fmaf(acc.y, di, b2[fl * 2 + 1]);
    }
}

extern "C" void kernel_launch(void* const* d_in, const int* in_sizes, int n_in,
                              void* d_out, int out_size) {
    const float* x  = (const float*)d_in[0];
    const int*   ei = (const int*)d_in[1];
    const float* W1 = (const float*)d_in[2];
    const float* b1 = (const float*)d_in[3];
    const float* W2 = (const float*)d_in[4];
    const float* b2 = (const float*)d_in[5];
    float* out = (float*)d_out;

    const int* src = ei;
    const int* dst = ei + NE;

    static bool init_done = false;
    static cudaStream_t s2;
    static cudaEvent_t ev_fork, ev_scan1, ev_join;
    static void* indeg_ptr = nullptr;
    if (!init_done) {
        cudaFuncSetAttribute(k_gemm1, cudaFuncAttributeMaxDynamicSharedMemorySize,
                             GEMM1_SMEM);
        cudaStreamCreateWithFlags(&s2, cudaStreamNonBlocking);
        cudaEventCreateWithFlags(&ev_fork, cudaEventDisableTiming);
        cudaEventCreateWithFlags(&ev_scan1, cudaEventDisableTiming);
        cudaEventCreateWithFlags(&ev_join, cudaEventDisableTiming);
        cudaGetSymbolAddress(&indeg_ptr, g_indeg);
        init_done = true;
    }

    // ---- fork immediately: gemm1 has no input deps ----
    cudaEventRecord(ev_fork, 0);
    cudaStreamWaitEvent(s2, ev_fork, 0);
    k_gemm1<<<(NN + 255) / 256, 256, GEMM1_SMEM, s2>>>(x, W1);

    // ---- prepass on capture stream, concurrent with gemm1 ----
    cudaMemsetAsync(indeg_ptr, 0, NN * sizeof(int), 0);
    k_indeg<<<(NE + 255) / 256, 256>>>(dst);
    k_scan1<<<NSCAN, SCAN_BLK>>>();
    cudaEventRecord(ev_scan1, 0);

    // s2: scale hs as soon as gemm1 + scan1 are both done (overlaps edge_pos)
    cudaStreamWaitEvent(s2, ev_scan1, 0);
    k_scale<<<(NN * 8 + 255) / 256, 256, 0, s2>>>();

    k_scan_apply<<<(NN + 255) / 256, 256>>>();
    k_edge_pos<<<(NE + 255) / 256, 256>>>(src, dst);

    // ---- join ----
    cudaEventRecord(ev_join, s2);
    cudaStreamWaitEvent(0, ev_join, 0);

    k_agg1<<<(NN * 32 + 255) / 256, 256>>>(b1);
    k_gemm2<<<(NN + 255) / 256, 256>>>(W2);
    k_agg2<<<(NN * 32 + 255) / 256, 256>>>(b2, out);
}